// round 15
// baseline (speedup 1.0000x reference)
#include <cuda_runtime.h>
#include <cuda_bf16.h>
#include <math.h>

#define BB 2
#define SS 2048
#define DIM 512
#define NT (BB*SS)
#define NH 8
#define DH 64
#define DC 2048
#define FFI 1365
#define FFIP 1408
#define NL 4

typedef __nv_bfloat16 bf16;

// ---------------- scratch (static device globals; no allocation) ----------------
__device__ float g_x[NT*DIM];
__device__ float g_femb[BB*(DIM+1)];
__device__ float g_cond[BB*DC];
__device__ float g_film[2*NL*BB*2*DIM];
__device__ float g_gate[2*NL*BB*DIM];
__device__ float g_b1p[NL*2*FFIP];
__device__ float g_part[8*2*NL*BB*2*DIM];
__device__ float g_sk[2][NT*DIM];          // split-K partials

// split-precision activation buffers
__device__ __align__(128) bf16 g_xin_h[NT*DIM],  g_xin_l[NT*DIM];
__device__ __align__(128) bf16 g_o_h[NT*DIM],    g_o_l[NT*DIM];
__device__ __align__(128) bf16 g_act_h[(size_t)NT*FFIP], g_act_l[(size_t)NT*FFIP];
// attention operands, [b][h][s][64] layout
__device__ __align__(128) bf16 g_q_h[NT*DIM], g_q_l[NT*DIM];
__device__ __align__(128) bf16 g_k_h[NT*DIM], g_k_l[NT*DIM];
__device__ __align__(128) bf16 g_v_h[NT*DIM], g_v_l[NT*DIM];
// split-precision weights (ff1 INTERLEAVED a/g columns; ff1/ff2 padded)
__device__ __align__(128) bf16 g_wqkv_h[NL*DIM*3*DIM], g_wqkv_l[NL*DIM*3*DIM];
__device__ __align__(128) bf16 g_wout_h[NL*DIM*DIM],   g_wout_l[NL*DIM*DIM];
__device__ __align__(128) bf16 g_wff1_h[(size_t)NL*DIM*2*FFIP], g_wff1_l[(size_t)NL*DIM*2*FFIP];
__device__ __align__(128) bf16 g_wff2_h[(size_t)NL*FFIP*DIM],   g_wff2_l[(size_t)NL*FFIP*DIM];

// ---------------- helpers ----------------
__device__ __forceinline__ void wsplit(float v, bf16* h, bf16* l, size_t idx) {
    bf16 hi = __float2bfloat16(v);
    h[idx] = hi;
    l[idx] = __float2bfloat16(v - __bfloat162float(hi));
}
__device__ __forceinline__ unsigned pack2(bf16 a, bf16 b) {
    unsigned short ua = *(unsigned short*)&a, ub = *(unsigned short*)&b;
    return (unsigned)ua | ((unsigned)ub << 16);
}
__device__ __forceinline__ unsigned packf2(float a, float b) {
    return pack2(__float2bfloat16(a), __float2bfloat16(b));
}
__device__ __forceinline__ void split4(float4 v, uint2& H, uint2& L) {
    bf16 h0 = __float2bfloat16(v.x), h1 = __float2bfloat16(v.y);
    bf16 h2 = __float2bfloat16(v.z), h3 = __float2bfloat16(v.w);
    H = make_uint2(pack2(h0, h1), pack2(h2, h3));
    L = make_uint2(packf2(v.x - __bfloat162float(h0), v.y - __bfloat162float(h1)),
                   packf2(v.z - __bfloat162float(h2), v.w - __bfloat162float(h3)));
}
__device__ __forceinline__ float tanh_ap(float x) {
    float y; asm("tanh.approx.f32 %0, %1;" : "=f"(y) : "f"(x)); return y;
}
__device__ __forceinline__ float warp_sum(float v) {
    #pragma unroll
    for (int o = 16; o > 0; o >>= 1) v += __shfl_xor_sync(0xffffffffu, v, o);
    return v;
}

__device__ __forceinline__ void mma16816(float* d, const unsigned* a, const unsigned* b) {
    asm volatile(
        "mma.sync.aligned.m16n8k16.row.col.f32.bf16.bf16.f32 "
        "{%0,%1,%2,%3}, {%4,%5,%6,%7}, {%8,%9}, {%0,%1,%2,%3};"
        : "+f"(d[0]), "+f"(d[1]), "+f"(d[2]), "+f"(d[3])
        : "r"(a[0]), "r"(a[1]), "r"(a[2]), "r"(a[3]), "r"(b[0]), "r"(b[1]));
}

#define LDSM_X4(r0,r1,r2,r3,addr) \
    asm volatile("ldmatrix.sync.aligned.m8n8.x4.shared.b16 {%0,%1,%2,%3}, [%4];" \
        : "=r"(r0),"=r"(r1),"=r"(r2),"=r"(r3) : "r"(addr))
#define LDSM_X4T(r0,r1,r2,r3,addr) \
    asm volatile("ldmatrix.sync.aligned.m8n8.x4.trans.shared.b16 {%0,%1,%2,%3}, [%4];" \
        : "=r"(r0),"=r"(r1),"=r"(r2),"=r"(r3) : "r"(addr))

__device__ __forceinline__ void cpa16(void* dst, const void* src) {
    unsigned d = (unsigned)__cvta_generic_to_shared(dst);
    asm volatile("cp.async.cg.shared.global [%0], [%1], 16;"
                 :: "r"(d), "l"(src) : "memory");
}
template<int W> __device__ __forceinline__ void cpwait() {
    asm volatile("cp.async.wait_group %0;" :: "n"(W) : "memory");
}
__device__ __forceinline__ void cpcommit() {
    asm volatile("cp.async.commit_group;" ::: "memory");
}

// ---------------- small kernels ----------------
__global__ void copy_x_kernel(const float* __restrict__ x) {
    int i = blockIdx.x * 256 + threadIdx.x;
    if (i < NT*DIM) g_x[i] = x[i];
}

__global__ void split_kernel(const float* __restrict__ s, bf16* __restrict__ h,
                             bf16* __restrict__ l, int n4) {
    int i = blockIdx.x * 256 + threadIdx.x;
    if (i >= n4) return;
    float4 v = ((const float4*)s)[i];
    uint2 H, L;
    split4(v, H, L);
    ((uint2*)h)[i] = H;
    ((uint2*)l)[i] = L;
}

// ff1 weights interleaved: out col 2c = a_c (src col c), 2c+1 = g_c (src col FFI+c)
__global__ void split_ff1_kernel(const float* __restrict__ s) {
    size_t i4 = (size_t)blockIdx.x * 256 + threadIdx.x;
    size_t total4 = (size_t)NL * DIM * 2 * FFIP / 4;
    if (i4 >= total4) return;
    size_t i = i4 * 4;
    int col = (int)(i % (2*FFIP));
    size_t rowg = i / (2*FFIP);
    const float* sr = s + rowg * (2*FFI);
    int c0 = col >> 1;
    float a0 = (c0 < FFI)   ? sr[c0]       : 0.f;
    float g0 = (c0 < FFI)   ? sr[FFI+c0]   : 0.f;
    float a1 = (c0+1 < FFI) ? sr[c0+1]     : 0.f;
    float g1 = (c0+1 < FFI) ? sr[FFI+c0+1] : 0.f;
    uint2 H, L;
    split4(make_float4(a0, g0, a1, g1), H, L);
    ((uint2*)g_wff1_h)[i4] = H;
    ((uint2*)g_wff1_l)[i4] = L;
}

__global__ void split_ff2_kernel(const float* __restrict__ s) {
    size_t i4 = (size_t)blockIdx.x * 256 + threadIdx.x;
    size_t total4 = (size_t)NL * FFIP * DIM / 4;
    if (i4 >= total4) return;
    size_t i = i4 * 4;
    int col = (int)(i % DIM);
    size_t rowg = i / DIM;
    int l = (int)(rowg / FFIP);
    int row = (int)(rowg % FFIP);
    float4 v = make_float4(0.f, 0.f, 0.f, 0.f);
    if (row < FFI) v = *(const float4*)(s + ((size_t)l*FFI + row) * DIM + col);
    uint2 H, L;
    split4(v, H, L);
    ((uint2*)g_wff2_h)[i4] = H;
    ((uint2*)g_wff2_l)[i4] = L;
}

__global__ void pad_b1_kernel(const float* __restrict__ s) {
    int i = blockIdx.x * 256 + threadIdx.x;
    if (i >= NL*2*FFIP) return;
    int col = i % (2*FFIP);
    int l = i / (2*FFIP);
    int c = col >> 1;
    float v = 0.f;
    if (c < FFI) v = s[l*(2*FFI) + ((col & 1) ? FFI : 0) + c];
    g_b1p[i] = v;
}

__global__ void femb_kernel(const float* __restrict__ times, const float* __restrict__ fw) {
    int i = blockIdx.x * blockDim.x + threadIdx.x;
    if (i >= BB*(DIM+1)) return;
    int b = i / (DIM+1), c = i % (DIM+1);
    float t = times[b];
    float v;
    if (c == 0) v = t;
    else if (c <= DIM/2) v = sinf(t * fw[c-1] * 6.283185307179586f);
    else v = cosf(t * fw[c-1-DIM/2] * 6.283185307179586f);
    g_femb[i] = v;
}

// ---------------- conditioning GEMMs ----------------
__global__ void cond_mm_kernel(const float* __restrict__ A, const float* __restrict__ W,
                               int N, int K, int kchunk, int KS) {
    int n = blockIdx.x * 128 + threadIdx.x;
    int m = blockIdx.y / KS, kc = blockIdx.y % KS;
    int k0 = kc * kchunk;
    int k1 = k0 + kchunk; if (k1 > K) k1 = K;
    const float* a = A + (size_t)m*K;
    float s = 0.f;
    #pragma unroll 4
    for (int k = k0; k < k1; k++) s += a[k] * __ldg(&W[(size_t)k*N + n]);
    g_part[((size_t)kc*BB + m)*N + n] = s;
}

__global__ void cond_reduce_kernel(const float* __restrict__ bias, float* __restrict__ out,
                                   int N, int KS, int act) {
    int i = blockIdx.x*256 + threadIdx.x;
    if (i >= BB*N) return;
    int n = i % N;
    int m = i / N;
    float s = bias[n];
    for (int kc = 0; kc < KS; kc++)
        s += g_part[((size_t)kc*BB + m)*N + n];
    if (act == 1) s = s / (1.f + expf(-s));
    out[i] = s;
}

// merged both-branch film/gate GEMMs: z in [0, 2*NL), br = z/NL, l = z%NL
__global__ void cond_mm2_kernel(const float* __restrict__ A,
                                const float* __restrict__ W0, const float* __restrict__ W1,
                                int N, int K, int kchunk, int KS) {
    int n = blockIdx.x * 128 + threadIdx.x;
    int m = blockIdx.y / KS, kc = blockIdx.y % KS;
    int z = blockIdx.z;
    int br = z / NL, l = z % NL;
    const float* w = (br ? W1 : W0) + (size_t)l*K*N;
    int k0 = kc * kchunk;
    int k1 = k0 + kchunk; if (k1 > K) k1 = K;
    const float* a = A + (size_t)m*K;
    float s = 0.f;
    #pragma unroll 4
    for (int k = k0; k < k1; k++) s += a[k] * __ldg(&w[(size_t)k*N + n]);
    g_part[(((size_t)kc*(2*NL) + z)*BB + m)*N + n] = s;
}

__global__ void cond_reduce2_kernel(const float* __restrict__ b0, const float* __restrict__ b1,
                                    float* __restrict__ out, int N, int KS, int act) {
    int i = blockIdx.x*256 + threadIdx.x;
    if (i >= 2*NL*BB*N) return;
    int z = i / (BB*N);
    int n = i % N;
    int m = (i / N) % BB;
    const float* bias = (z < NL) ? b0 + (size_t)z*N : b1 + (size_t)(z-NL)*N;
    float s = bias[n];
    for (int kc = 0; kc < KS; kc++)
        s += g_part[(((size_t)kc*(2*NL) + z)*BB + m)*N + n];
    if (act == 2) s = 1.f / (1.f + expf(-s));
    out[i] = s;
}

// ---------------- modulate: warp-per-row, shfl-only reductions ----------------
__global__ void __launch_bounds__(256) modulate_kernel(const float* __restrict__ src,
                                bf16* __restrict__ dh, bf16* __restrict__ dl,
                                const float* __restrict__ film,
                                const float* __restrict__ ln_g,
                                const float* __restrict__ norm_g,
                                const int* __restrict__ mod) {
    int row = blockIdx.x * 8 + (threadIdx.x >> 5);
    int lane = threadIdx.x & 31;
    int b = row / SS;
    const float* xr = src + (size_t)row * DIM;

    float4 v[4];
    float s = 0.f;
    #pragma unroll
    for (int j = 0; j < 4; j++) {
        v[j] = *(const float4*)(xr + j*128 + lane*4);
        s += v[j].x + v[j].y + v[j].z + v[j].w;
    }
    float mean = warp_sum(s) * (1.f/DIM);
    float vv = 0.f;
    #pragma unroll
    for (int j = 0; j < 4; j++) {
        float d0 = v[j].x-mean, d1 = v[j].y-mean, d2 = v[j].z-mean, d3 = v[j].w-mean;
        vv += d0*d0 + d1*d1 + d2*d2 + d3*d3;
    }
    float rstd = rsqrtf(warp_sum(vv) * (1.f/DIM) + 1e-5f);

    bool m = mod[row] != 0;
    float4 xmod[4];
    float ss = 0.f;
    #pragma unroll
    for (int j = 0; j < 4; j++) {
        float4 g4, b4;
        if (m) {
            const float* f = film + (size_t)b * 2 * DIM;
            g4 = *(const float4*)(f + j*128 + lane*4);
            b4 = *(const float4*)(f + DIM + j*128 + lane*4);
        } else {
            g4 = *(const float4*)(ln_g + j*128 + lane*4);
            b4 = make_float4(0.f, 0.f, 0.f, 0.f);
        }
        xmod[j].x = (v[j].x-mean)*rstd*(g4.x+1.f) + b4.x;
        xmod[j].y = (v[j].y-mean)*rstd*(g4.y+1.f) + b4.y;
        xmod[j].z = (v[j].z-mean)*rstd*(g4.z+1.f) + b4.z;
        xmod[j].w = (v[j].w-mean)*rstd*(g4.w+1.f) + b4.w;
        ss += xmod[j].x*xmod[j].x + xmod[j].y*xmod[j].y
            + xmod[j].z*xmod[j].z + xmod[j].w*xmod[j].w;
    }
    float n = sqrtf(warp_sum(ss));
    float sc = 22.62741699796952f / fmaxf(n, 1e-12f);

    size_t base = (size_t)row * DIM;
    #pragma unroll
    for (int j = 0; j < 4; j++) {
        float4 n4 = *(const float4*)(norm_g + j*128 + lane*4);
        float4 y;
        y.x = xmod[j].x * sc * (n4.x+1.f);
        y.y = xmod[j].y * sc * (n4.y+1.f);
        y.z = xmod[j].z * sc * (n4.z+1.f);
        y.w = xmod[j].w * sc * (n4.w+1.f);
        uint2 H, L;
        split4(y, H, L);
        *(uint2*)&dh[base + j*128 + lane*4] = H;
        *(uint2*)&dl[base + j*128 + lane*4] = L;
    }
}

// ---------------- tensor-core split-bf16 GEMM, cp.async 2-stage pipeline ----------------
// modes: 0 = C (+bias) fp32; 1 = qkv split write; 2 = gated residual into g_x;
//        3 = interleaved GEGLU -> split g_act; 4 = split-K partial (C + z*M*N)
#define LDA 40
#define LDB 136
#define STG 18944
#define GEMM_SMEM (2*STG*2)

__device__ __forceinline__ void gemm_issue(bf16* st, const bf16* Ah, const bf16* Al,
        const bf16* Bh, const bf16* Bl, int bm, int bn, int N, int K, int k0, int tid) {
    #pragma unroll
    for (int hl = 0; hl < 2; hl++) {
        const bf16* a = hl ? Al : Ah;
        bf16* as = st + hl*5120;
        #pragma unroll
        for (int i = 0; i < 2; i++) {
            int ch = i*256 + tid;
            int row = ch >> 2, kc = (ch & 3)*8;
            cpa16(as + row*LDA + kc, a + (size_t)(bm+row)*K + k0 + kc);
        }
        const bf16* b = hl ? Bl : Bh;
        bf16* bs = st + 10240 + hl*4352;
        #pragma unroll
        for (int i = 0; i < 2; i++) {
            int ch = i*256 + tid;
            int kr = ch >> 4, nc = (ch & 15)*8;
            cpa16(bs + kr*LDB + nc, b + (size_t)(k0+kr)*N + bn + nc);
        }
    }
    cpcommit();
}

__global__ void __launch_bounds__(256) mma_gemm_kernel(
        const bf16* __restrict__ Ah, const bf16* __restrict__ Al,
        const bf16* __restrict__ Bh, const bf16* __restrict__ Bl,
        const float* __restrict__ bias, float* __restrict__ C,
        int M, int N, int K, int mode,
        const float* __restrict__ gate, const float* __restrict__ lscale,
        const int* __restrict__ mod) {
    extern __shared__ __align__(16) bf16 dsm[];
    int tid = threadIdx.x, lane = tid & 31, wid = tid >> 5;
    int bm = blockIdx.y * 128, bn = blockIdx.x * 128;
    int mf = (wid >> 1) * 32, nf = (wid & 1) * 64;

    int kspan = K / (int)gridDim.z;
    int kbase = (int)blockIdx.z * kspan;

    float acc[2][8][4];
    #pragma unroll
    for (int i = 0; i < 2; i++)
        #pragma unroll
        for (int j = 0; j < 8; j++)
            #pragma unroll
            for (int r = 0; r < 4; r++) acc[i][j][r] = 0.f;

    int a_m = mf + (lane & 7) + ((lane >> 3) & 1) * 8;
    int a_k = (lane >> 4) * 8;
    int b_k = (lane & 7) + ((lane >> 3) & 1) * 8;
    int b_n = nf + (lane >> 4) * 8;

    int niter = kspan >> 5;
    gemm_issue(dsm, Ah, Al, Bh, Bl, bm, bn, N, K, kbase, tid);

    for (int it = 0; it < niter; it++) {
        if (it + 1 < niter) {
            gemm_issue(dsm + ((it+1) & 1)*STG, Ah, Al, Bh, Bl, bm, bn, N, K,
                       kbase + ((it+1) << 5), tid);
            cpwait<1>();
        } else {
            cpwait<0>();
        }
        __syncthreads();
        bf16* As0 = dsm + (it & 1)*STG;
        bf16* As1 = As0 + 5120;
        bf16* Bs0 = As0 + 10240;
        bf16* Bs1 = Bs0 + 4352;

        #pragma unroll
        for (int kk = 0; kk < 32; kk += 16) {
            unsigned af[2][2][4];
            #pragma unroll
            for (int hl = 0; hl < 2; hl++) {
                bf16* as = hl ? As1 : As0;
                #pragma unroll
                for (int mi = 0; mi < 2; mi++) {
                    unsigned sa = (unsigned)__cvta_generic_to_shared(
                        &as[(a_m + mi*16)*LDA + kk + a_k]);
                    LDSM_X4(af[hl][mi][0], af[hl][mi][1], af[hl][mi][2], af[hl][mi][3], sa);
                }
            }
            unsigned bfr[2][8][2];
            #pragma unroll
            for (int hl = 0; hl < 2; hl++) {
                bf16* bs = hl ? Bs1 : Bs0;
                #pragma unroll
                for (int np = 0; np < 4; np++) {
                    unsigned sa = (unsigned)__cvta_generic_to_shared(
                        &bs[(kk + b_k)*LDB + b_n + np*16]);
                    unsigned r0, r1, r2, r3;
                    LDSM_X4T(r0, r1, r2, r3, sa);
                    bfr[hl][np*2][0]   = r0; bfr[hl][np*2][1]   = r1;
                    bfr[hl][np*2+1][0] = r2; bfr[hl][np*2+1][1] = r3;
                }
            }
            #pragma unroll
            for (int mi = 0; mi < 2; mi++)
                #pragma unroll
                for (int nj = 0; nj < 8; nj++) {
                    mma16816(acc[mi][nj], af[0][mi], bfr[0][nj]);
                    mma16816(acc[mi][nj], af[0][mi], bfr[1][nj]);
                    mma16816(acc[mi][nj], af[1][mi], bfr[0][nj]);
                }
        }
        __syncthreads();
    }

    // ---- epilogue ----
    if (mode == 0) {
        #pragma unroll
        for (int mi = 0; mi < 2; mi++) {
            int r0 = bm + mf + mi*16 + (lane >> 2);
            #pragma unroll
            for (int nj = 0; nj < 8; nj++) {
                int c0 = bn + nf + nj*8 + (lane & 3)*2;
                float b0 = bias ? bias[c0] : 0.f;
                float b1 = bias ? bias[c0+1] : 0.f;
                C[(size_t)r0*N + c0]       = acc[mi][nj][0] + b0;
                C[(size_t)(r0+8)*N + c0]   = acc[mi][nj][2] + b0;
                C[(size_t)r0*N + c0+1]     = acc[mi][nj][1] + b1;
                C[(size_t)(r0+8)*N + c0+1] = acc[mi][nj][3] + b1;
            }
        }
    } else if (mode == 1) {
        #pragma unroll
        for (int mi = 0; mi < 2; mi++) {
            int m0 = bm + mf + mi*16 + (lane >> 2);
            #pragma unroll
            for (int nj = 0; nj < 8; nj++) {
                int c0 = bn + nf + nj*8 + (lane & 3)*2;
                int c3 = c0 >> 9;
                int hh = (c0 & 511) >> 6;
                int d  = c0 & 63;
                float sc = (c3 == 0) ? 0.125f : 1.f;
                bf16* H = (c3 == 0) ? g_q_h : (c3 == 1 ? g_k_h : g_v_h);
                bf16* L = (c3 == 0) ? g_q_l : (c3 == 1 ? g_k_l : g_v_l);
                #pragma unroll
                for (int rr = 0; rr < 2; rr++) {
                    int m = m0 + rr*8;
                    float v0 = acc[mi][nj][rr*2]   * sc;
                    float v1 = acc[mi][nj][rr*2+1] * sc;
                    size_t o = ((size_t)((m/SS)*NH + hh)*SS + (m % SS))*DH + d;
                    bf16 h0 = __float2bfloat16(v0), h1 = __float2bfloat16(v1);
                    *(unsigned*)&H[o] = pack2(h0, h1);
                    *(unsigned*)&L[o] = packf2(v0 - __bfloat162float(h0),
                                               v1 - __bfloat162float(h1));
                }
            }
        }
    } else if (mode == 2) {
        #pragma unroll
        for (int mi = 0; mi < 2; mi++) {
            int m0 = bm + mf + mi*16 + (lane >> 2);
            #pragma unroll
            for (int nj = 0; nj < 8; nj++) {
                int c0 = bn + nf + nj*8 + (lane & 3)*2;
                #pragma unroll
                for (int rr = 0; rr < 2; rr++) {
                    int m = m0 + rr*8;
                    bool mm = mod[m] != 0;
                    int bidx = m / SS;
                    #pragma unroll
                    for (int e = 0; e < 2; e++) {
                        int c = c0 + e;
                        float v = acc[mi][nj][rr*2 + e];
                        if (bias) v += bias[c];
                        float r = mm ? v * gate[bidx*DIM + c] : v * lscale[c];
                        g_x[(size_t)m*DIM + c] += r;
                    }
                }
            }
        }
    } else if (mode == 3) {
        // interleaved GEGLU epilogue -> split bf16 g_act
        #pragma unroll
        for (int mi = 0; mi < 2; mi++) {
            int m0 = bm + mf + mi*16 + (lane >> 2);
            #pragma unroll
            for (int nj = 0; nj < 8; nj++) {
                int c0 = bn + nf + nj*8 + (lane & 3)*2;
                int cc = c0 >> 1;
                float ba = bias[c0], bg = bias[c0+1];
                #pragma unroll
                for (int rr = 0; rr < 2; rr++) {
                    int m = m0 + rr*8;
                    float a = acc[mi][nj][rr*2]   + ba;
                    float g = acc[mi][nj][rr*2+1] + bg;
                    float ge = 0.5f * g * (1.f + erff(g * 0.7071067811865475f));
                    wsplit(ge * a, g_act_h, g_act_l, (size_t)m*FFIP + cc);
                }
            }
        }
    } else {
        // mode 4: split-K partial write
        float* dst = C + (size_t)blockIdx.z * ((size_t)M * N);
        #pragma unroll
        for (int mi = 0; mi < 2; mi++) {
            int r0 = bm + mf + mi*16 + (lane >> 2);
            #pragma unroll
            for (int nj = 0; nj < 8; nj++) {
                int c0 = bn + nf + nj*8 + (lane & 3)*2;
                dst[(size_t)r0*N + c0]       = acc[mi][nj][0];
                dst[(size_t)(r0+8)*N + c0]   = acc[mi][nj][2];
                dst[(size_t)r0*N + c0+1]     = acc[mi][nj][1];
                dst[(size_t)(r0+8)*N + c0+1] = acc[mi][nj][3];
            }
        }
    }
}

// split-K reduce + gated residual into g_x (N = DIM)
__global__ void skres_kernel(const float* __restrict__ bias,
                             const float* __restrict__ gate,
                             const float* __restrict__ lscale,
                             const int* __restrict__ mod) {
    int i4 = blockIdx.x * 256 + threadIdx.x;
    if (i4 >= NT*DIM/4) return;
    int i = i4 * 4;
    int row = i / DIM, c = i % DIM;
    bool mm = mod[row] != 0;
    int b = row / SS;
    float4 v0 = ((const float4*)g_sk[0])[i4];
    float4 v1 = ((const float4*)g_sk[1])[i4];
    float4 bb = bias ? *(const float4*)(bias + c) : make_float4(0.f,0.f,0.f,0.f);
    const float* gsrc = mm ? (gate + b*DIM) : lscale;
    float4 g4 = *(const float4*)(gsrc + c);
    float4 xo = ((const float4*)g_x)[i4];
    xo.x += (v0.x + v1.x + bb.x) * g4.x;
    xo.y += (v0.y + v1.y + bb.y) * g4.y;
    xo.z += (v0.z + v1.z + bb.z) * g4.z;
    xo.w += (v0.w + v1.w + bb.w) * g4.w;
    ((float4*)g_x)[i4] = xo;
}

// ---------------- tensor-core flash attention ----------------
// 256 threads, 128 q-rows/block (8 warps x 16 rows), 64-key tiles,
// cp.async double-buffered, longest-work blocks launch first.
#define FP 72
#define FSTG (4*64*FP)
#define FLASH_SMEM (2*FSTG*2)

__device__ __forceinline__ void flash_issue(bf16* st, size_t base, int jt, int tid) {
    #pragma unroll
    for (int i2 = 0; i2 < 2; i2++) {
        int e = i2*256 + tid;
        int key = e >> 3, dg = (e & 7) * 8;
        size_t g = base + (size_t)(jt + key)*DH + dg;
        int so = key*FP + dg;
        cpa16(st + so,         g_k_h + g);
        cpa16(st + 4608 + so,  g_k_l + g);
        cpa16(st + 9216 + so,  g_v_h + g);
        cpa16(st + 13824 + so, g_v_l + g);
    }
    cpcommit();
}

__global__ void __launch_bounds__(256) flash_mma_kernel() {
    extern __shared__ __align__(16) bf16 fsm[];
    int tid = threadIdx.x, lane = tid & 31, w = tid >> 5;
    int q0 = ((SS/128) - 1 - (int)blockIdx.x) * 128;    // reversed: longest first
    int h = blockIdx.y, b = blockIdx.z;
    size_t base = ((size_t)(b*NH + h))*SS*DH;
    int r = lane >> 2, c2 = (lane & 3) * 2;
    int qr0 = q0 + w*16 + r;
    int wmin = q0 + w*16;            // warp's lowest q-row
    int wmax = q0 + w*16 + 15;       // warp's highest q-row

    unsigned qf[2][4][4];
    #pragma unroll
    for (int kt = 0; kt < 4; kt++) {
        size_t p0 = base + (size_t)qr0*DH + kt*16 + c2;
        size_t p1 = base + (size_t)(qr0+8)*DH + kt*16 + c2;
        qf[0][kt][0] = *(const unsigned*)(g_q_h + p0);
        qf[0][kt][1] = *(const unsigned*)(g_q_h + p1);
        qf[0][kt][2] = *(const unsigned*)(g_q_h + p0 + 8);
        qf[0][kt][3] = *(const unsigned*)(g_q_h + p1 + 8);
        qf[1][kt][0] = *(const unsigned*)(g_q_l + p0);
        qf[1][kt][1] = *(const unsigned*)(g_q_l + p1);
        qf[1][kt][2] = *(const unsigned*)(g_q_l + p0 + 8);
        qf[1][kt][3] = *(const unsigned*)(g_q_l + p1 + 8);
    }

    float oa[8][4];
    #pragma unroll
    for (int i = 0; i < 8; i++)
        #pragma unroll
        for (int e = 0; e < 4; e++) oa[i][e] = 0.f;
    float m0 = -1e30f, m1 = -1e30f, l0 = 0.f, l1 = 0.f;

    int klg = lane >> 3, klr = lane & 7;
    int kkey = (klg >> 1) * 8 + klr;
    int kd8 = (klg & 1) * 8;
    int vbk = (lane & 7) + ((lane >> 3) & 1) * 8;
    int vbn = (lane >> 4) * 8;

    int nt = (q0 >> 6) + 2;          // tiles covering keys 0..q0+127
    flash_issue(fsm, base, 0, tid);

    for (int it = 0; it < nt; it++) {
        int jt = it << 6;
        if (it + 1 < nt) {
            flash_issue(fsm + ((it+1) & 1)*FSTG, base, jt + 64, tid);
            cpwait<1>();
        } else {
            cpwait<0>();
        }
        __syncthreads();
        if (jt <= wmax) {            // warp has at least one unmasked row
        bf16* Ksh = fsm + (it & 1)*FSTG;
        bf16* Ksl = Ksh + 4608;
        bf16* Vsh = Ksh + 9216;
        bf16* Vsl = Ksh + 13824;

        float sa[8][4];
        #pragma unroll
        for (int njp = 0; njp < 4; njp++) {
            #pragma unroll
            for (int e = 0; e < 4; e++) { sa[njp*2][e] = 0.f; sa[njp*2+1][e] = 0.f; }
            #pragma unroll
            for (int kt = 0; kt < 4; kt++) {
                unsigned kh0,kh1,kh2,kh3, kl0,kl1,kl2,kl3;
                unsigned ah = (unsigned)__cvta_generic_to_shared(
                    &Ksh[(njp*16 + kkey)*FP + kt*16 + kd8]);
                unsigned al = (unsigned)__cvta_generic_to_shared(
                    &Ksl[(njp*16 + kkey)*FP + kt*16 + kd8]);
                LDSM_X4(kh0, kh1, kh2, kh3, ah);
                LDSM_X4(kl0, kl1, kl2, kl3, al);
                unsigned bh0[2] = {kh0,kh1}, bh1[2] = {kh2,kh3};
                unsigned bl0[2] = {kl0,kl1}, bl1[2] = {kl2,kl3};
                mma16816(sa[njp*2],   qf[0][kt], bh0);
                mma16816(sa[njp*2],   qf[0][kt], bl0);
                mma16816(sa[njp*2],   qf[1][kt], bh0);
                mma16816(sa[njp*2+1], qf[0][kt], bh1);
                mma16816(sa[njp*2+1], qf[0][kt], bl1);
                mma16816(sa[njp*2+1], qf[1][kt], bh1);
            }
        }

        bool diag = (jt + 63 > wmin);
        float mx0 = -1e30f, mx1 = -1e30f;
        #pragma unroll
        for (int nj = 0; nj < 8; nj++) {
            #pragma unroll
            for (int e = 0; e < 4; e++) {
                float s = 50.f * tanh_ap(sa[nj][e] * 0.02f);
                if (diag) {
                    int jc = jt + nj*8 + c2 + (e & 1);
                    int qr = qr0 + ((e >> 1) ? 8 : 0);
                    if (jc > qr) s = -1e30f;
                }
                sa[nj][e] = s;
                if (e < 2) mx0 = fmaxf(mx0, s); else mx1 = fmaxf(mx1, s);
            }
        }
        mx0 = fmaxf(mx0, __shfl_xor_sync(0xffffffffu, mx0, 1));
        mx0 = fmaxf(mx0, __shfl_xor_sync(0xffffffffu, mx0, 2));
        mx1 = fmaxf(mx1, __shfl_xor_sync(0xffffffffu, mx1, 1));
        mx1 = fmaxf(mx1, __shfl_xor_sync(0xffffffffu, mx1, 2));
        float mn0 = fmaxf(m0, mx0), mn1 = fmaxf(m1, mx1);
        float cr0 = __expf(m0 - mn0), cr1 = __expf(m1 - mn1);
        m0 = mn0; m1 = mn1;

        float ls0 = 0.f, ls1 = 0.f;
        unsigned pf[2][4][4];
        #pragma unroll
        for (int nj = 0; nj < 8; nj++) {
            float p0 = __expf(sa[nj][0] - mn0);
            float p1 = __expf(sa[nj][1] - mn0);
            float p2 = __expf(sa[nj][2] - mn1);
            float p3 = __expf(sa[nj][3] - mn1);
            ls0 += p0 + p1; ls1 += p2 + p3;
            bf16 h0 = __float2bfloat16(p0), h1b = __float2bfloat16(p1);
            bf16 h2 = __float2bfloat16(p2), h3b = __float2bfloat16(p3);
            int kt = nj >> 1, off = (nj & 1) * 2;
            pf[0][kt][off]   = pack2(h0, h1b);
            pf[0][kt][off+1] = pack2(h2, h3b);
            pf[1][kt][off]   = packf2(p0 - __bfloat162float(h0), p1 - __bfloat162float(h1b));
            pf[1][kt][off+1] = packf2(p2 - __bfloat162float(h2), p3 - __bfloat162float(h3b));
        }
        ls0 += __shfl_xor_sync(0xffffffffu, ls0, 1);
        ls0 += __shfl_xor_sync(0xffffffffu, ls0, 2);
        ls1 += __shfl_xor_sync(0xffffffffu, ls1, 1);
        ls1 += __shfl_xor_sync(0xffffffffu, ls1, 2);
        l0 = l0 * cr0 + ls0;
        l1 = l1 * cr1 + ls1;
        #pragma unroll
        for (int od = 0; od < 8; od++) {
            oa[od][0] *= cr0; oa[od][1] *= cr0;
            oa[od][2] *= cr1; oa[od][3] *= cr1;
        }

        #pragma unroll
        for (int kt = 0; kt < 4; kt++) {
            #pragma unroll
            for (int odp = 0; odp < 4; odp++) {
                unsigned vh0,vh1,vh2,vh3, vl0,vl1,vl2,vl3;
                unsigned ah = (unsigned)__cvta_generic_to_shared(
                    &Vsh[(kt*16 + vbk)*FP + odp*16 + vbn]);
                unsigned al = (unsigned)__cvta_generic_to_shared(
                    &Vsl[(kt*16 + vbk)*FP + odp*16 + vbn]);
                LDSM_X4T(vh0, vh1, vh2, vh3, ah);
                LDSM_X4T(vl0, vl1, vl2, vl3, al);
                unsigned bvh0[2] = {vh0,vh1}, bvh1[2] = {vh2,vh3};
                unsigned bvl0[2] = {vl0,vl1}, bvl1[2] = {vl2,vl3};
                mma16816(oa[odp*2],   pf[0][kt], bvh0);
                mma16816(oa[odp*2],   pf[0][kt], bvl0);
                mma16816(oa[odp*2],   pf[1][kt], bvh0);
                mma16816(oa[odp*2+1], pf[0][kt], bvh1);
                mma16816(oa[odp*2+1], pf[0][kt], bvl1);
                mma16816(oa[odp*2+1], pf[1][kt], bvh1);
            }
        }
        }  // warp skip
        __syncthreads();
    }

    float i0 = 1.f / l0, i1 = 1.f / l1;
    size_t t0 = ((size_t)(b*SS + qr0))*DIM + h*DH;
    size_t t1 = t0 + (size_t)8*DIM;
    #pragma unroll
    for (int od = 0; od < 8; od++) {
        int col = od*8 + c2;
        float v0 = oa[od][0]*i0, v1 = oa[od][1]*i0;
        float v2 = oa[od][2]*i1, v3 = oa[od][3]*i1;
        bf16 h0 = __float2bfloat16(v0), h1b = __float2bfloat16(v1);
        bf16 h2 = __float2bfloat16(v2), h3b = __float2bfloat16(v3);
        *(unsigned*)&g_o_h[t0 + col] = pack2(h0, h1b);
        *(unsigned*)&g_o_l[t0 + col] = packf2(v0 - __bfloat162float(h0), v1 - __bfloat162float(h1b));
        *(unsigned*)&g_o_h[t1 + col] = pack2(h2, h3b);
        *(unsigned*)&g_o_l[t1 + col] = packf2(v2 - __bfloat162float(h2), v3 - __bfloat162float(h3b));
    }
}

// ---------------- final rmsnorm: warp-per-row ----------------
__global__ void __launch_bounds__(256) final_rmsnorm_kernel(const float* __restrict__ fg,
                                                            float* __restrict__ out) {
    int row = blockIdx.x * 8 + (threadIdx.x >> 5);
    int lane = threadIdx.x & 31;
    const float* xr = g_x + (size_t)row * DIM;
    float4 v[4];
    float ss = 0.f;
    #pragma unroll
    for (int j = 0; j < 4; j++) {
        v[j] = *(const float4*)(xr + j*128 + lane*4);
        ss += v[j].x*v[j].x + v[j].y*v[j].y + v[j].z*v[j].z + v[j].w*v[j].w;
    }
    float n = sqrtf(warp_sum(ss));
    float sc = 22.62741699796952f / fmaxf(n, 1e-12f);
    float* outr = out + (size_t)row * DIM;
    #pragma unroll
    for (int j = 0; j < 4; j++) {
        float4 g4 = *(const float4*)(fg + j*128 + lane*4);
        float4 y;
        y.x = v[j].x * sc * (g4.x+1.f);
        y.y = v[j].y * sc * (g4.y+1.f);
        y.z = v[j].z * sc * (g4.z+1.f);
        y.w = v[j].w * sc * (g4.w+1.f);
        *(float4*)(outr + j*128 + lane*4) = y;
    }
}

// ---------------- host ----------------
extern "C" void kernel_launch(void* const* d_in, const int* in_sizes, int n_in,
                              void* d_out, int out_size) {
    const float* x          = (const float*)d_in[0];
    const float* times      = (const float*)d_in[1];
    const int* mod          = (const int*)d_in[3];
    const float* fourier_w  = (const float*)d_in[4];
    const float* time_w     = (const float*)d_in[5];
    const float* time_b     = (const float*)d_in[6];
    const float* aw_ln_g    = (const float*)d_in[7];
    const float* aw_scale   = (const float*)d_in[8];
    const float* aw_film_w  = (const float*)d_in[9];
    const float* aw_film_b  = (const float*)d_in[10];
    const float* aw_zero_w  = (const float*)d_in[11];
    const float* aw_zero_b  = (const float*)d_in[12];
    const float* attn_norm_g= (const float*)d_in[13];
    const float* qkv_w      = (const float*)d_in[14];
    const float* out_w      = (const float*)d_in[15];
    const float* fw_ln_g    = (const float*)d_in[16];
    const float* fw_scale   = (const float*)d_in[17];
    const float* fw_film_w  = (const float*)d_in[18];
    const float* fw_film_b  = (const float*)d_in[19];
    const float* fw_zero_w  = (const float*)d_in[20];
    const float* fw_zero_b  = (const float*)d_in[21];
    const float* ff_norm_g  = (const float*)d_in[22];
    const float* ff_w1      = (const float*)d_in[23];
    const float* ff_b1      = (const float*)d_in[24];
    const float* ff_w2      = (const float*)d_in[25];
    const float* ff_b2      = (const float*)d_in[26];
    const float* final_g    = (const float*)d_in[27];
    float* out = (float*)d_out;

    float *p_femb, *p_cond, *p_film, *p_gate, *p_x, *p_b1p, *p_sk;
    bf16 *p_xin_h, *p_xin_l, *p_o_h, *p_o_l, *p_act_h, *p_act_l;
    bf16 *p_wqkv_h, *p_wqkv_l, *p_wout_h, *p_wout_l, *p_wff1_h, *p_wff1_l, *p_wff2_h, *p_wff2_l;
    cudaGetSymbolAddress((void**)&p_femb, g_femb);
    cudaGetSymbolAddress((void**)&p_cond, g_cond);
    cudaGetSymbolAddress((void**)&p_film, g_film);
    cudaGetSymbolAddress((void**)&p_gate, g_gate);
    cudaGetSymbolAddress((void**)&p_x,    g_x);
    cudaGetSymbolAddress((void**)&p_b1p,  g_b1p);
    cudaGetSymbolAddress((void**)&p_sk,   g_sk);
    cudaGetSymbolAddress((void**)&p_xin_h, g_xin_h);
    cudaGetSymbolAddress((void**)&p_xin_l, g_xin_l);
    cudaGetSymbolAddress((void**)&p_o_h,   g_o_h);
    cudaGetSymbolAddress((void**)&p_o_l,   g_o_l);
    cudaGetSymbolAddress((void**)&p_act_h, g_act_h);
    cudaGetSymbolAddress((void**)&p_act_l, g_act_l);
    cudaGetSymbolAddress((void**)&p_wqkv_h, g_wqkv_h);
    cudaGetSymbolAddress((void**)&p_wqkv_l, g_wqkv_l);
    cudaGetSymbolAddress((void**)&p_wout_h, g_wout_h);
    cudaGetSymbolAddress((void**)&p_wout_l, g_wout_l);
    cudaGetSymbolAddress((void**)&p_wff1_h, g_wff1_h);
    cudaGetSymbolAddress((void**)&p_wff1_l, g_wff1_l);
    cudaGetSymbolAddress((void**)&p_wff2_h, g_wff2_h);
    cudaGetSymbolAddress((void**)&p_wff2_l, g_wff2_l);

    static bool attr_set = false;
    if (!attr_set) {
        cudaFuncSetAttribute(mma_gemm_kernel,
                             cudaFuncAttributeMaxDynamicSharedMemorySize, GEMM_SMEM);
        cudaFuncSetAttribute(flash_mma_kernel,
                             cudaFuncAttributeMaxDynamicSharedMemorySize, FLASH_SMEM);
        attr_set = true;
    }

    copy_x_kernel<<<(NT*DIM + 255)/256, 256>>>(x);

    {
        int n1 = NL*DIM*3*DIM/4;
        split_kernel<<<(n1+255)/256, 256>>>(qkv_w, p_wqkv_h, p_wqkv_l, n1);
        int n2 = NL*DIM*DIM/4;
        split_kernel<<<(n2+255)/256, 256>>>(out_w, p_wout_h, p_wout_l, n2);
        size_t n3 = (size_t)NL*DIM*2*FFIP/4;
        split_ff1_kernel<<<(unsigned)((n3+255)/256), 256>>>(ff_w1);
        size_t n4 = (size_t)NL*FFIP*DIM/4;
        split_ff2_kernel<<<(unsigned)((n4+255)/256), 256>>>(ff_w2);
        pad_b1_kernel<<<(NL*2*FFIP+255)/256, 256>>>(ff_b1);
    }

    femb_kernel<<<(BB*(DIM+1) + 255)/256, 256>>>(times, fourier_w);
    cond_mm_kernel<<<dim3(DC/128, BB*4, 1), 128>>>(p_femb, time_w, DC, DIM+1, 129, 4);
    cond_reduce_kernel<<<(BB*DC+255)/256, 256>>>(time_b, p_cond, DC, 4, 1);

    cond_mm2_kernel<<<dim3((2*DIM)/128, BB*8, 2*NL), 128>>>(
        p_cond, aw_film_w, fw_film_w, 2*DIM, DC, 256, 8);
    cond_reduce2_kernel<<<(2*NL*BB*2*DIM+255)/256, 256>>>(
        aw_film_b, fw_film_b, p_film, 2*DIM, 8, 0);
    cond_mm2_kernel<<<dim3(DIM/128, BB*8, 2*NL), 128>>>(
        p_cond, aw_zero_w, fw_zero_w, DIM, DC, 256, 8);
    cond_reduce2_kernel<<<(2*NL*BB*DIM+255)/256, 256>>>(
        aw_zero_b, fw_zero_b, p_gate, DIM, 8, 2);

    for (int l = 0; l < NL; l++) {
        // ---- attention branch ----
        modulate_kernel<<<NT/8, 256>>>(p_x, p_xin_h, p_xin_l,
            p_film + ((size_t)(0*NL + l))*BB*2*DIM,
            aw_ln_g + (size_t)l*DIM, attn_norm_g + (size_t)l*DIM, mod);
        mma_gemm_kernel<<<dim3((3*DIM)/128, NT/128), 256, GEMM_SMEM>>>(
            p_xin_h, p_xin_l,
            p_wqkv_h + (size_t)l*DIM*3*DIM, p_wqkv_l + (size_t)l*DIM*3*DIM,
            nullptr, nullptr, NT, 3*DIM, DIM, 1, nullptr, nullptr, nullptr);
        flash_mma_kernel<<<dim3(SS/128, NH, BB), 256, FLASH_SMEM>>>();
        mma_gemm_kernel<<<dim3(DIM/128, NT/128, 2), 256, GEMM_SMEM>>>(
            p_o_h, p_o_l,
            p_wout_h + (size_t)l*DIM*DIM, p_wout_l + (size_t)l*DIM*DIM,
            nullptr, p_sk, NT, DIM, DIM, 4, nullptr, nullptr, nullptr);
        skres_kernel<<<(NT*DIM/4 + 255)/256, 256>>>(
            nullptr, p_gate + ((size_t)(0*NL + l))*BB*DIM, aw_scale + (size_t)l*DIM, mod);

        // ---- feedforward branch ----
        modulate_kernel<<<NT/8, 256>>>(p_x, p_xin_h, p_xin_l,
            p_film + ((size_t)(1*NL + l))*BB*2*DIM,
            fw_ln_g + (size_t)l*DIM, ff_norm_g + (size_t)l*DIM, mod);
        mma_gemm_kernel<<<dim3((2*FFIP)/128, NT/128), 256, GEMM_SMEM>>>(
            p_xin_h, p_xin_l,
            p_wff1_h + (size_t)l*DIM*2*FFIP, p_wff1_l + (size_t)l*DIM*2*FFIP,
            p_b1p + (size_t)l*2*FFIP, nullptr, NT, 2*FFIP, DIM, 3, nullptr, nullptr, nullptr);
        mma_gemm_kernel<<<dim3(DIM/128, NT/128, 2), 256, GEMM_SMEM>>>(
            p_act_h, p_act_l,
            p_wff2_h + (size_t)l*FFIP*DIM, p_wff2_l + (size_t)l*FFIP*DIM,
            nullptr, p_sk, NT, DIM, FFIP, 4, nullptr, nullptr, nullptr);
        skres_kernel<<<(NT*DIM/4 + 255)/256, 256>>>(
            ff_b2 + (size_t)l*DIM, p_gate + ((size_t)(1*NL + l))*BB*DIM,
            fw_scale + (size_t)l*DIM, mod);
    }

    final_rmsnorm_kernel<<<NT/8, 256>>>(final_g, out);
}

// round 16
// speedup vs baseline: 1.0846x; 1.0846x over previous
#include <cuda_runtime.h>
#include <cuda_bf16.h>
#include <math.h>

#define BB 2
#define SS 2048
#define DIM 512
#define NT (BB*SS)
#define NH 8
#define DH 64
#define DC 2048
#define FFI 1365
#define FFIP 1408
#define NL 4

typedef __nv_bfloat16 bf16;

// ---------------- scratch (static device globals; no allocation) ----------------
__device__ float g_x[NT*DIM];
__device__ float g_femb[BB*(DIM+1)];
__device__ float g_cond[BB*DC];
__device__ float g_film[2*NL*BB*2*DIM];
__device__ float g_gate[2*NL*BB*DIM];
__device__ float g_b1p[NL*2*FFIP];
__device__ float g_part[8*2*NL*BB*2*DIM];
__device__ float g_sk[2][NT*DIM];          // split-K partials

// split-precision activation buffers
__device__ __align__(128) bf16 g_xin_h[NT*DIM],  g_xin_l[NT*DIM];
__device__ __align__(128) bf16 g_o_h[NT*DIM],    g_o_l[NT*DIM];
__device__ __align__(128) bf16 g_act_h[(size_t)NT*FFIP], g_act_l[(size_t)NT*FFIP];
// attention operands, [b][h][s][64] layout
__device__ __align__(128) bf16 g_q_h[NT*DIM], g_q_l[NT*DIM];
__device__ __align__(128) bf16 g_k_h[NT*DIM], g_k_l[NT*DIM];
__device__ __align__(128) bf16 g_v_h[NT*DIM], g_v_l[NT*DIM];
// split-precision weights (ff1 INTERLEAVED a/g columns; ff1/ff2 padded)
__device__ __align__(128) bf16 g_wqkv_h[NL*DIM*3*DIM], g_wqkv_l[NL*DIM*3*DIM];
__device__ __align__(128) bf16 g_wout_h[NL*DIM*DIM],   g_wout_l[NL*DIM*DIM];
__device__ __align__(128) bf16 g_wff1_h[(size_t)NL*DIM*2*FFIP], g_wff1_l[(size_t)NL*DIM*2*FFIP];
__device__ __align__(128) bf16 g_wff2_h[(size_t)NL*FFIP*DIM],   g_wff2_l[(size_t)NL*FFIP*DIM];

// ---------------- helpers ----------------
__device__ __forceinline__ void wsplit(float v, bf16* h, bf16* l, size_t idx) {
    bf16 hi = __float2bfloat16(v);
    h[idx] = hi;
    l[idx] = __float2bfloat16(v - __bfloat162float(hi));
}
__device__ __forceinline__ unsigned pack2(bf16 a, bf16 b) {
    unsigned short ua = *(unsigned short*)&a, ub = *(unsigned short*)&b;
    return (unsigned)ua | ((unsigned)ub << 16);
}
__device__ __forceinline__ unsigned packf2(float a, float b) {
    return pack2(__float2bfloat16(a), __float2bfloat16(b));
}
__device__ __forceinline__ void split4(float4 v, uint2& H, uint2& L) {
    bf16 h0 = __float2bfloat16(v.x), h1 = __float2bfloat16(v.y);
    bf16 h2 = __float2bfloat16(v.z), h3 = __float2bfloat16(v.w);
    H = make_uint2(pack2(h0, h1), pack2(h2, h3));
    L = make_uint2(packf2(v.x - __bfloat162float(h0), v.y - __bfloat162float(h1)),
                   packf2(v.z - __bfloat162float(h2), v.w - __bfloat162float(h3)));
}
__device__ __forceinline__ float tanh_ap(float x) {
    float y; asm("tanh.approx.f32 %0, %1;" : "=f"(y) : "f"(x)); return y;
}
__device__ __forceinline__ float warp_sum(float v) {
    #pragma unroll
    for (int o = 16; o > 0; o >>= 1) v += __shfl_xor_sync(0xffffffffu, v, o);
    return v;
}

__device__ __forceinline__ void mma16816(float* d, const unsigned* a, const unsigned* b) {
    asm volatile(
        "mma.sync.aligned.m16n8k16.row.col.f32.bf16.bf16.f32 "
        "{%0,%1,%2,%3}, {%4,%5,%6,%7}, {%8,%9}, {%0,%1,%2,%3};"
        : "+f"(d[0]), "+f"(d[1]), "+f"(d[2]), "+f"(d[3])
        : "r"(a[0]), "r"(a[1]), "r"(a[2]), "r"(a[3]), "r"(b[0]), "r"(b[1]));
}

#define LDSM_X4(r0,r1,r2,r3,addr) \
    asm volatile("ldmatrix.sync.aligned.m8n8.x4.shared.b16 {%0,%1,%2,%3}, [%4];" \
        : "=r"(r0),"=r"(r1),"=r"(r2),"=r"(r3) : "r"(addr))
#define LDSM_X4T(r0,r1,r2,r3,addr) \
    asm volatile("ldmatrix.sync.aligned.m8n8.x4.trans.shared.b16 {%0,%1,%2,%3}, [%4];" \
        : "=r"(r0),"=r"(r1),"=r"(r2),"=r"(r3) : "r"(addr))

__device__ __forceinline__ void cpa16(void* dst, const void* src) {
    unsigned d = (unsigned)__cvta_generic_to_shared(dst);
    asm volatile("cp.async.cg.shared.global [%0], [%1], 16;"
                 :: "r"(d), "l"(src) : "memory");
}
template<int W> __device__ __forceinline__ void cpwait() {
    asm volatile("cp.async.wait_group %0;" :: "n"(W) : "memory");
}
__device__ __forceinline__ void cpcommit() {
    asm volatile("cp.async.commit_group;" ::: "memory");
}

// ---------------- small kernels ----------------
__global__ void copy_x_kernel(const float* __restrict__ x) {
    int i = blockIdx.x * 256 + threadIdx.x;
    if (i < NT*DIM) g_x[i] = x[i];
}

__global__ void split_kernel(const float* __restrict__ s, bf16* __restrict__ h,
                             bf16* __restrict__ l, int n4) {
    int i = blockIdx.x * 256 + threadIdx.x;
    if (i >= n4) return;
    float4 v = ((const float4*)s)[i];
    uint2 H, L;
    split4(v, H, L);
    ((uint2*)h)[i] = H;
    ((uint2*)l)[i] = L;
}

// ff1 weights interleaved: out col 2c = a_c (src col c), 2c+1 = g_c (src col FFI+c)
__global__ void split_ff1_kernel(const float* __restrict__ s) {
    size_t i4 = (size_t)blockIdx.x * 256 + threadIdx.x;
    size_t total4 = (size_t)NL * DIM * 2 * FFIP / 4;
    if (i4 >= total4) return;
    size_t i = i4 * 4;
    int col = (int)(i % (2*FFIP));
    size_t rowg = i / (2*FFIP);
    const float* sr = s + rowg * (2*FFI);
    int c0 = col >> 1;
    float a0 = (c0 < FFI)   ? sr[c0]       : 0.f;
    float g0 = (c0 < FFI)   ? sr[FFI+c0]   : 0.f;
    float a1 = (c0+1 < FFI) ? sr[c0+1]     : 0.f;
    float g1 = (c0+1 < FFI) ? sr[FFI+c0+1] : 0.f;
    uint2 H, L;
    split4(make_float4(a0, g0, a1, g1), H, L);
    ((uint2*)g_wff1_h)[i4] = H;
    ((uint2*)g_wff1_l)[i4] = L;
}

__global__ void split_ff2_kernel(const float* __restrict__ s) {
    size_t i4 = (size_t)blockIdx.x * 256 + threadIdx.x;
    size_t total4 = (size_t)NL * FFIP * DIM / 4;
    if (i4 >= total4) return;
    size_t i = i4 * 4;
    int col = (int)(i % DIM);
    size_t rowg = i / DIM;
    int l = (int)(rowg / FFIP);
    int row = (int)(rowg % FFIP);
    float4 v = make_float4(0.f, 0.f, 0.f, 0.f);
    if (row < FFI) v = *(const float4*)(s + ((size_t)l*FFI + row) * DIM + col);
    uint2 H, L;
    split4(v, H, L);
    ((uint2*)g_wff2_h)[i4] = H;
    ((uint2*)g_wff2_l)[i4] = L;
}

__global__ void pad_b1_kernel(const float* __restrict__ s) {
    int i = blockIdx.x * 256 + threadIdx.x;
    if (i >= NL*2*FFIP) return;
    int col = i % (2*FFIP);
    int l = i / (2*FFIP);
    int c = col >> 1;
    float v = 0.f;
    if (c < FFI) v = s[l*(2*FFI) + ((col & 1) ? FFI : 0) + c];
    g_b1p[i] = v;
}

__global__ void femb_kernel(const float* __restrict__ times, const float* __restrict__ fw) {
    int i = blockIdx.x * blockDim.x + threadIdx.x;
    if (i >= BB*(DIM+1)) return;
    int b = i / (DIM+1), c = i % (DIM+1);
    float t = times[b];
    float v;
    if (c == 0) v = t;
    else if (c <= DIM/2) v = sinf(t * fw[c-1] * 6.283185307179586f);
    else v = cosf(t * fw[c-1-DIM/2] * 6.283185307179586f);
    g_femb[i] = v;
}

// ---------------- conditioning GEMMs ----------------
__global__ void cond_mm_kernel(const float* __restrict__ A, const float* __restrict__ W,
                               int N, int K, int kchunk, int KS) {
    int n = blockIdx.x * 128 + threadIdx.x;
    int m = blockIdx.y / KS, kc = blockIdx.y % KS;
    int k0 = kc * kchunk;
    int k1 = k0 + kchunk; if (k1 > K) k1 = K;
    const float* a = A + (size_t)m*K;
    float s = 0.f;
    #pragma unroll 4
    for (int k = k0; k < k1; k++) s += a[k] * __ldg(&W[(size_t)k*N + n]);
    g_part[((size_t)kc*BB + m)*N + n] = s;
}

__global__ void cond_reduce_kernel(const float* __restrict__ bias, float* __restrict__ out,
                                   int N, int KS, int act) {
    int i = blockIdx.x*256 + threadIdx.x;
    if (i >= BB*N) return;
    int n = i % N;
    int m = i / N;
    float s = bias[n];
    for (int kc = 0; kc < KS; kc++)
        s += g_part[((size_t)kc*BB + m)*N + n];
    if (act == 1) s = s / (1.f + expf(-s));
    out[i] = s;
}

// merged both-branch film/gate GEMMs: z in [0, 2*NL), br = z/NL, l = z%NL
__global__ void cond_mm2_kernel(const float* __restrict__ A,
                                const float* __restrict__ W0, const float* __restrict__ W1,
                                int N, int K, int kchunk, int KS) {
    int n = blockIdx.x * 128 + threadIdx.x;
    int m = blockIdx.y / KS, kc = blockIdx.y % KS;
    int z = blockIdx.z;
    int br = z / NL, l = z % NL;
    const float* w = (br ? W1 : W0) + (size_t)l*K*N;
    int k0 = kc * kchunk;
    int k1 = k0 + kchunk; if (k1 > K) k1 = K;
    const float* a = A + (size_t)m*K;
    float s = 0.f;
    #pragma unroll 4
    for (int k = k0; k < k1; k++) s += a[k] * __ldg(&w[(size_t)k*N + n]);
    g_part[(((size_t)kc*(2*NL) + z)*BB + m)*N + n] = s;
}

__global__ void cond_reduce2_kernel(const float* __restrict__ b0, const float* __restrict__ b1,
                                    float* __restrict__ out, int N, int KS, int act) {
    int i = blockIdx.x*256 + threadIdx.x;
    if (i >= 2*NL*BB*N) return;
    int z = i / (BB*N);
    int n = i % N;
    int m = (i / N) % BB;
    const float* bias = (z < NL) ? b0 + (size_t)z*N : b1 + (size_t)(z-NL)*N;
    float s = bias[n];
    for (int kc = 0; kc < KS; kc++)
        s += g_part[(((size_t)kc*(2*NL) + z)*BB + m)*N + n];
    if (act == 2) s = 1.f / (1.f + expf(-s));
    out[i] = s;
}

// ---------------- modulate: warp-per-row, shfl-only reductions ----------------
__global__ void __launch_bounds__(256) modulate_kernel(const float* __restrict__ src,
                                bf16* __restrict__ dh, bf16* __restrict__ dl,
                                const float* __restrict__ film,
                                const float* __restrict__ ln_g,
                                const float* __restrict__ norm_g,
                                const int* __restrict__ mod) {
    int row = blockIdx.x * 8 + (threadIdx.x >> 5);
    int lane = threadIdx.x & 31;
    int b = row / SS;
    const float* xr = src + (size_t)row * DIM;

    float4 v[4];
    float s = 0.f;
    #pragma unroll
    for (int j = 0; j < 4; j++) {
        v[j] = *(const float4*)(xr + j*128 + lane*4);
        s += v[j].x + v[j].y + v[j].z + v[j].w;
    }
    float mean = warp_sum(s) * (1.f/DIM);
    float vv = 0.f;
    #pragma unroll
    for (int j = 0; j < 4; j++) {
        float d0 = v[j].x-mean, d1 = v[j].y-mean, d2 = v[j].z-mean, d3 = v[j].w-mean;
        vv += d0*d0 + d1*d1 + d2*d2 + d3*d3;
    }
    float rstd = rsqrtf(warp_sum(vv) * (1.f/DIM) + 1e-5f);

    bool m = mod[row] != 0;
    float4 xmod[4];
    float ss = 0.f;
    #pragma unroll
    for (int j = 0; j < 4; j++) {
        float4 g4, b4;
        if (m) {
            const float* f = film + (size_t)b * 2 * DIM;
            g4 = *(const float4*)(f + j*128 + lane*4);
            b4 = *(const float4*)(f + DIM + j*128 + lane*4);
        } else {
            g4 = *(const float4*)(ln_g + j*128 + lane*4);
            b4 = make_float4(0.f, 0.f, 0.f, 0.f);
        }
        xmod[j].x = (v[j].x-mean)*rstd*(g4.x+1.f) + b4.x;
        xmod[j].y = (v[j].y-mean)*rstd*(g4.y+1.f) + b4.y;
        xmod[j].z = (v[j].z-mean)*rstd*(g4.z+1.f) + b4.z;
        xmod[j].w = (v[j].w-mean)*rstd*(g4.w+1.f) + b4.w;
        ss += xmod[j].x*xmod[j].x + xmod[j].y*xmod[j].y
            + xmod[j].z*xmod[j].z + xmod[j].w*xmod[j].w;
    }
    float n = sqrtf(warp_sum(ss));
    float sc = 22.62741699796952f / fmaxf(n, 1e-12f);

    size_t base = (size_t)row * DIM;
    #pragma unroll
    for (int j = 0; j < 4; j++) {
        float4 n4 = *(const float4*)(norm_g + j*128 + lane*4);
        float4 y;
        y.x = xmod[j].x * sc * (n4.x+1.f);
        y.y = xmod[j].y * sc * (n4.y+1.f);
        y.z = xmod[j].z * sc * (n4.z+1.f);
        y.w = xmod[j].w * sc * (n4.w+1.f);
        uint2 H, L;
        split4(y, H, L);
        *(uint2*)&dh[base + j*128 + lane*4] = H;
        *(uint2*)&dl[base + j*128 + lane*4] = L;
    }
}

// ---------------- tensor-core split-bf16 GEMM, cp.async 2-stage pipeline ----------------
// modes: 0 = C (+bias) fp32; 1 = qkv split write; 2 = gated residual into g_x;
//        3 = interleaved GEGLU -> split g_act; 4 = split-K partial (C + z*M*N)
#define LDA 40
#define LDB 136
#define STG 18944
#define GEMM_SMEM (2*STG*2)

__device__ __forceinline__ void gemm_issue(bf16* st, const bf16* Ah, const bf16* Al,
        const bf16* Bh, const bf16* Bl, int bm, int bn, int N, int K, int k0, int tid) {
    #pragma unroll
    for (int hl = 0; hl < 2; hl++) {
        const bf16* a = hl ? Al : Ah;
        bf16* as = st + hl*5120;
        #pragma unroll
        for (int i = 0; i < 2; i++) {
            int ch = i*256 + tid;
            int row = ch >> 2, kc = (ch & 3)*8;
            cpa16(as + row*LDA + kc, a + (size_t)(bm+row)*K + k0 + kc);
        }
        const bf16* b = hl ? Bl : Bh;
        bf16* bs = st + 10240 + hl*4352;
        #pragma unroll
        for (int i = 0; i < 2; i++) {
            int ch = i*256 + tid;
            int kr = ch >> 4, nc = (ch & 15)*8;
            cpa16(bs + kr*LDB + nc, b + (size_t)(k0+kr)*N + bn + nc);
        }
    }
    cpcommit();
}

__global__ void __launch_bounds__(256) mma_gemm_kernel(
        const bf16* __restrict__ Ah, const bf16* __restrict__ Al,
        const bf16* __restrict__ Bh, const bf16* __restrict__ Bl,
        const float* __restrict__ bias, float* __restrict__ C,
        int M, int N, int K, int mode,
        const float* __restrict__ gate, const float* __restrict__ lscale,
        const int* __restrict__ mod) {
    extern __shared__ __align__(16) bf16 dsm[];
    int tid = threadIdx.x, lane = tid & 31, wid = tid >> 5;
    int bm = blockIdx.y * 128, bn = blockIdx.x * 128;
    int mf = (wid >> 1) * 32, nf = (wid & 1) * 64;

    int kspan = K / (int)gridDim.z;
    int kbase = (int)blockIdx.z * kspan;

    float acc[2][8][4];
    #pragma unroll
    for (int i = 0; i < 2; i++)
        #pragma unroll
        for (int j = 0; j < 8; j++)
            #pragma unroll
            for (int r = 0; r < 4; r++) acc[i][j][r] = 0.f;

    int a_m = mf + (lane & 7) + ((lane >> 3) & 1) * 8;
    int a_k = (lane >> 4) * 8;
    int b_k = (lane & 7) + ((lane >> 3) & 1) * 8;
    int b_n = nf + (lane >> 4) * 8;

    int niter = kspan >> 5;
    gemm_issue(dsm, Ah, Al, Bh, Bl, bm, bn, N, K, kbase, tid);

    for (int it = 0; it < niter; it++) {
        if (it + 1 < niter) {
            gemm_issue(dsm + ((it+1) & 1)*STG, Ah, Al, Bh, Bl, bm, bn, N, K,
                       kbase + ((it+1) << 5), tid);
            cpwait<1>();
        } else {
            cpwait<0>();
        }
        __syncthreads();
        bf16* As0 = dsm + (it & 1)*STG;
        bf16* As1 = As0 + 5120;
        bf16* Bs0 = As0 + 10240;
        bf16* Bs1 = Bs0 + 4352;

        #pragma unroll
        for (int kk = 0; kk < 32; kk += 16) {
            unsigned af[2][2][4];
            #pragma unroll
            for (int hl = 0; hl < 2; hl++) {
                bf16* as = hl ? As1 : As0;
                #pragma unroll
                for (int mi = 0; mi < 2; mi++) {
                    unsigned sa = (unsigned)__cvta_generic_to_shared(
                        &as[(a_m + mi*16)*LDA + kk + a_k]);
                    LDSM_X4(af[hl][mi][0], af[hl][mi][1], af[hl][mi][2], af[hl][mi][3], sa);
                }
            }
            unsigned bfr[2][8][2];
            #pragma unroll
            for (int hl = 0; hl < 2; hl++) {
                bf16* bs = hl ? Bs1 : Bs0;
                #pragma unroll
                for (int np = 0; np < 4; np++) {
                    unsigned sa = (unsigned)__cvta_generic_to_shared(
                        &bs[(kk + b_k)*LDB + b_n + np*16]);
                    unsigned r0, r1, r2, r3;
                    LDSM_X4T(r0, r1, r2, r3, sa);
                    bfr[hl][np*2][0]   = r0; bfr[hl][np*2][1]   = r1;
                    bfr[hl][np*2+1][0] = r2; bfr[hl][np*2+1][1] = r3;
                }
            }
            #pragma unroll
            for (int mi = 0; mi < 2; mi++)
                #pragma unroll
                for (int nj = 0; nj < 8; nj++) {
                    mma16816(acc[mi][nj], af[0][mi], bfr[0][nj]);
                    mma16816(acc[mi][nj], af[0][mi], bfr[1][nj]);
                    mma16816(acc[mi][nj], af[1][mi], bfr[0][nj]);
                }
        }
        __syncthreads();
    }

    // ---- epilogue ----
    if (mode == 0) {
        #pragma unroll
        for (int mi = 0; mi < 2; mi++) {
            int r0 = bm + mf + mi*16 + (lane >> 2);
            #pragma unroll
            for (int nj = 0; nj < 8; nj++) {
                int c0 = bn + nf + nj*8 + (lane & 3)*2;
                float b0 = bias ? bias[c0] : 0.f;
                float b1 = bias ? bias[c0+1] : 0.f;
                C[(size_t)r0*N + c0]       = acc[mi][nj][0] + b0;
                C[(size_t)(r0+8)*N + c0]   = acc[mi][nj][2] + b0;
                C[(size_t)r0*N + c0+1]     = acc[mi][nj][1] + b1;
                C[(size_t)(r0+8)*N + c0+1] = acc[mi][nj][3] + b1;
            }
        }
    } else if (mode == 1) {
        #pragma unroll
        for (int mi = 0; mi < 2; mi++) {
            int m0 = bm + mf + mi*16 + (lane >> 2);
            #pragma unroll
            for (int nj = 0; nj < 8; nj++) {
                int c0 = bn + nf + nj*8 + (lane & 3)*2;
                int c3 = c0 >> 9;
                int hh = (c0 & 511) >> 6;
                int d  = c0 & 63;
                float sc = (c3 == 0) ? 0.125f : 1.f;
                bf16* H = (c3 == 0) ? g_q_h : (c3 == 1 ? g_k_h : g_v_h);
                bf16* L = (c3 == 0) ? g_q_l : (c3 == 1 ? g_k_l : g_v_l);
                #pragma unroll
                for (int rr = 0; rr < 2; rr++) {
                    int m = m0 + rr*8;
                    float v0 = acc[mi][nj][rr*2]   * sc;
                    float v1 = acc[mi][nj][rr*2+1] * sc;
                    size_t o = ((size_t)((m/SS)*NH + hh)*SS + (m % SS))*DH + d;
                    bf16 h0 = __float2bfloat16(v0), h1 = __float2bfloat16(v1);
                    *(unsigned*)&H[o] = pack2(h0, h1);
                    *(unsigned*)&L[o] = packf2(v0 - __bfloat162float(h0),
                                               v1 - __bfloat162float(h1));
                }
            }
        }
    } else if (mode == 2) {
        #pragma unroll
        for (int mi = 0; mi < 2; mi++) {
            int m0 = bm + mf + mi*16 + (lane >> 2);
            #pragma unroll
            for (int nj = 0; nj < 8; nj++) {
                int c0 = bn + nf + nj*8 + (lane & 3)*2;
                #pragma unroll
                for (int rr = 0; rr < 2; rr++) {
                    int m = m0 + rr*8;
                    bool mm = mod[m] != 0;
                    int bidx = m / SS;
                    #pragma unroll
                    for (int e = 0; e < 2; e++) {
                        int c = c0 + e;
                        float v = acc[mi][nj][rr*2 + e];
                        if (bias) v += bias[c];
                        float r = mm ? v * gate[bidx*DIM + c] : v * lscale[c];
                        g_x[(size_t)m*DIM + c] += r;
                    }
                }
            }
        }
    } else if (mode == 3) {
        // interleaved GEGLU epilogue -> split bf16 g_act
        #pragma unroll
        for (int mi = 0; mi < 2; mi++) {
            int m0 = bm + mf + mi*16 + (lane >> 2);
            #pragma unroll
            for (int nj = 0; nj < 8; nj++) {
                int c0 = bn + nf + nj*8 + (lane & 3)*2;
                int cc = c0 >> 1;
                float ba = bias[c0], bg = bias[c0+1];
                #pragma unroll
                for (int rr = 0; rr < 2; rr++) {
                    int m = m0 + rr*8;
                    float a = acc[mi][nj][rr*2]   + ba;
                    float g = acc[mi][nj][rr*2+1] + bg;
                    float ge = 0.5f * g * (1.f + erff(g * 0.7071067811865475f));
                    wsplit(ge * a, g_act_h, g_act_l, (size_t)m*FFIP + cc);
                }
            }
        }
    } else {
        // mode 4: split-K partial write
        float* dst = C + (size_t)blockIdx.z * ((size_t)M * N);
        #pragma unroll
        for (int mi = 0; mi < 2; mi++) {
            int r0 = bm + mf + mi*16 + (lane >> 2);
            #pragma unroll
            for (int nj = 0; nj < 8; nj++) {
                int c0 = bn + nf + nj*8 + (lane & 3)*2;
                dst[(size_t)r0*N + c0]       = acc[mi][nj][0];
                dst[(size_t)(r0+8)*N + c0]   = acc[mi][nj][2];
                dst[(size_t)r0*N + c0+1]     = acc[mi][nj][1];
                dst[(size_t)(r0+8)*N + c0+1] = acc[mi][nj][3];
            }
        }
    }
}

// split-K reduce + gated residual into g_x (N = DIM)
__global__ void skres_kernel(const float* __restrict__ bias,
                             const float* __restrict__ gate,
                             const float* __restrict__ lscale,
                             const int* __restrict__ mod) {
    int i4 = blockIdx.x * 256 + threadIdx.x;
    if (i4 >= NT*DIM/4) return;
    int i = i4 * 4;
    int row = i / DIM, c = i % DIM;
    bool mm = mod[row] != 0;
    int b = row / SS;
    float4 v0 = ((const float4*)g_sk[0])[i4];
    float4 v1 = ((const float4*)g_sk[1])[i4];
    float4 bb = bias ? *(const float4*)(bias + c) : make_float4(0.f,0.f,0.f,0.f);
    const float* gsrc = mm ? (gate + b*DIM) : lscale;
    float4 g4 = *(const float4*)(gsrc + c);
    float4 xo = ((const float4*)g_x)[i4];
    xo.x += (v0.x + v1.x + bb.x) * g4.x;
    xo.y += (v0.y + v1.y + bb.y) * g4.y;
    xo.z += (v0.z + v1.z + bb.z) * g4.z;
    xo.w += (v0.w + v1.w + bb.w) * g4.w;
    ((float4*)g_x)[i4] = xo;
}

// ---------------- tensor-core flash attention ----------------
// 128 threads, 64 q-rows/block, 64-key tiles, cp.async double-buffered.
// Block order reversed: longest-work blocks launch first.
#define FP 72
#define FSTG (4*64*FP)
#define FLASH_SMEM (2*FSTG*2)

__device__ __forceinline__ void flash_issue(bf16* st, size_t base, int jt, int tid) {
    #pragma unroll
    for (int i2 = 0; i2 < 4; i2++) {
        int e = i2*128 + tid;
        int key = e >> 3, dg = (e & 7) * 8;
        size_t g = base + (size_t)(jt + key)*DH + dg;
        int so = key*FP + dg;
        cpa16(st + so,         g_k_h + g);
        cpa16(st + 4608 + so,  g_k_l + g);
        cpa16(st + 9216 + so,  g_v_h + g);
        cpa16(st + 13824 + so, g_v_l + g);
    }
    cpcommit();
}

__global__ void __launch_bounds__(128) flash_mma_kernel() {
    extern __shared__ __align__(16) bf16 fsm[];
    int tid = threadIdx.x, lane = tid & 31, w = tid >> 5;
    int q0 = ((SS/64) - 1 - (int)blockIdx.x) * 64;   // reversed: longest first
    int h = blockIdx.y, b = blockIdx.z;
    size_t base = ((size_t)(b*NH + h))*SS*DH;
    int r = lane >> 2, c2 = (lane & 3) * 2;
    int qr0 = q0 + w*16 + r;

    unsigned qf[2][4][4];
    #pragma unroll
    for (int kt = 0; kt < 4; kt++) {
        size_t p0 = base + (size_t)qr0*DH + kt*16 + c2;
        size_t p1 = base + (size_t)(qr0+8)*DH + kt*16 + c2;
        qf[0][kt][0] = *(const unsigned*)(g_q_h + p0);
        qf[0][kt][1] = *(const unsigned*)(g_q_h + p1);
        qf[0][kt][2] = *(const unsigned*)(g_q_h + p0 + 8);
        qf[0][kt][3] = *(const unsigned*)(g_q_h + p1 + 8);
        qf[1][kt][0] = *(const unsigned*)(g_q_l + p0);
        qf[1][kt][1] = *(const unsigned*)(g_q_l + p1);
        qf[1][kt][2] = *(const unsigned*)(g_q_l + p0 + 8);
        qf[1][kt][3] = *(const unsigned*)(g_q_l + p1 + 8);
    }

    float oa[8][4];
    #pragma unroll
    for (int i = 0; i < 8; i++)
        #pragma unroll
        for (int e = 0; e < 4; e++) oa[i][e] = 0.f;
    float m0 = -1e30f, m1 = -1e30f, l0 = 0.f, l1 = 0.f;

    int klg = lane >> 3, klr = lane & 7;
    int kkey = (klg >> 1) * 8 + klr;
    int kd8 = (klg & 1) * 8;
    int vbk = (lane & 7) + ((lane >> 3) & 1) * 8;
    int vbn = (lane >> 4) * 8;

    int nt = (q0 >> 6) + 1;
    flash_issue(fsm, base, 0, tid);

    for (int it = 0; it < nt; it++) {
        int jt = it << 6;
        if (it + 1 < nt) {
            flash_issue(fsm + ((it+1) & 1)*FSTG, base, jt + 64, tid);
            cpwait<1>();
        } else {
            cpwait<0>();
        }
        __syncthreads();
        bf16* Ksh = fsm + (it & 1)*FSTG;
        bf16* Ksl = Ksh + 4608;
        bf16* Vsh = Ksh + 9216;
        bf16* Vsl = Ksh + 13824;

        float sa[8][4];
        #pragma unroll
        for (int njp = 0; njp < 4; njp++) {
            #pragma unroll
            for (int e = 0; e < 4; e++) { sa[njp*2][e] = 0.f; sa[njp*2+1][e] = 0.f; }
            #pragma unroll
            for (int kt = 0; kt < 4; kt++) {
                unsigned kh0,kh1,kh2,kh3, kl0,kl1,kl2,kl3;
                unsigned ah = (unsigned)__cvta_generic_to_shared(
                    &Ksh[(njp*16 + kkey)*FP + kt*16 + kd8]);
                unsigned al = (unsigned)__cvta_generic_to_shared(
                    &Ksl[(njp*16 + kkey)*FP + kt*16 + kd8]);
                LDSM_X4(kh0, kh1, kh2, kh3, ah);
                LDSM_X4(kl0, kl1, kl2, kl3, al);
                unsigned bh0[2] = {kh0,kh1}, bh1[2] = {kh2,kh3};
                unsigned bl0[2] = {kl0,kl1}, bl1[2] = {kl2,kl3};
                mma16816(sa[njp*2],   qf[0][kt], bh0);
                mma16816(sa[njp*2],   qf[0][kt], bl0);
                mma16816(sa[njp*2],   qf[1][kt], bh0);
                mma16816(sa[njp*2+1], qf[0][kt], bh1);
                mma16816(sa[njp*2+1], qf[0][kt], bl1);
                mma16816(sa[njp*2+1], qf[1][kt], bh1);
            }
        }

        bool diag = (jt == q0);
        float mx0 = -1e30f, mx1 = -1e30f;
        #pragma unroll
        for (int nj = 0; nj < 8; nj++) {
            #pragma unroll
            for (int e = 0; e < 4; e++) {
                float s = 50.f * tanh_ap(sa[nj][e] * 0.02f);
                if (diag) {
                    int jc = jt + nj*8 + c2 + (e & 1);
                    int qr = qr0 + ((e >> 1) ? 8 : 0);
                    if (jc > qr) s = -1e30f;
                }
                sa[nj][e] = s;
                if (e < 2) mx0 = fmaxf(mx0, s); else mx1 = fmaxf(mx1, s);
            }
        }
        mx0 = fmaxf(mx0, __shfl_xor_sync(0xffffffffu, mx0, 1));
        mx0 = fmaxf(mx0, __shfl_xor_sync(0xffffffffu, mx0, 2));
        mx1 = fmaxf(mx1, __shfl_xor_sync(0xffffffffu, mx1, 1));
        mx1 = fmaxf(mx1, __shfl_xor_sync(0xffffffffu, mx1, 2));
        float mn0 = fmaxf(m0, mx0), mn1 = fmaxf(m1, mx1);
        float cr0 = __expf(m0 - mn0), cr1 = __expf(m1 - mn1);
        m0 = mn0; m1 = mn1;

        float ls0 = 0.f, ls1 = 0.f;
        unsigned pf[2][4][4];
        #pragma unroll
        for (int nj = 0; nj < 8; nj++) {
            float p0 = __expf(sa[nj][0] - mn0);
            float p1 = __expf(sa[nj][1] - mn0);
            float p2 = __expf(sa[nj][2] - mn1);
            float p3 = __expf(sa[nj][3] - mn1);
            ls0 += p0 + p1; ls1 += p2 + p3;
            bf16 h0 = __float2bfloat16(p0), h1b = __float2bfloat16(p1);
            bf16 h2 = __float2bfloat16(p2), h3b = __float2bfloat16(p3);
            int kt = nj >> 1, off = (nj & 1) * 2;
            pf[0][kt][off]   = pack2(h0, h1b);
            pf[0][kt][off+1] = pack2(h2, h3b);
            pf[1][kt][off]   = packf2(p0 - __bfloat162float(h0), p1 - __bfloat162float(h1b));
            pf[1][kt][off+1] = packf2(p2 - __bfloat162float(h2), p3 - __bfloat162float(h3b));
        }
        ls0 += __shfl_xor_sync(0xffffffffu, ls0, 1);
        ls0 += __shfl_xor_sync(0xffffffffu, ls0, 2);
        ls1 += __shfl_xor_sync(0xffffffffu, ls1, 1);
        ls1 += __shfl_xor_sync(0xffffffffu, ls1, 2);
        l0 = l0 * cr0 + ls0;
        l1 = l1 * cr1 + ls1;
        #pragma unroll
        for (int od = 0; od < 8; od++) {
            oa[od][0] *= cr0; oa[od][1] *= cr0;
            oa[od][2] *= cr1; oa[od][3] *= cr1;
        }

        #pragma unroll
        for (int kt = 0; kt < 4; kt++) {
            #pragma unroll
            for (int odp = 0; odp < 4; odp++) {
                unsigned vh0,vh1,vh2,vh3, vl0,vl1,vl2,vl3;
                unsigned ah = (unsigned)__cvta_generic_to_shared(
                    &Vsh[(kt*16 + vbk)*FP + odp*16 + vbn]);
                unsigned al = (unsigned)__cvta_generic_to_shared(
                    &Vsl[(kt*16 + vbk)*FP + odp*16 + vbn]);
                LDSM_X4T(vh0, vh1, vh2, vh3, ah);
                LDSM_X4T(vl0, vl1, vl2, vl3, al);
                unsigned bvh0[2] = {vh0,vh1}, bvh1[2] = {vh2,vh3};
                unsigned bvl0[2] = {vl0,vl1}, bvl1[2] = {vl2,vl3};
                mma16816(oa[odp*2],   pf[0][kt], bvh0);
                mma16816(oa[odp*2],   pf[0][kt], bvl0);
                mma16816(oa[odp*2],   pf[1][kt], bvh0);
                mma16816(oa[odp*2+1], pf[0][kt], bvh1);
                mma16816(oa[odp*2+1], pf[0][kt], bvl1);
                mma16816(oa[odp*2+1], pf[1][kt], bvh1);
            }
        }
        __syncthreads();
    }

    float i0 = 1.f / l0, i1 = 1.f / l1;
    size_t t0 = ((size_t)(b*SS + qr0))*DIM + h*DH;
    size_t t1 = t0 + (size_t)8*DIM;
    #pragma unroll
    for (int od = 0; od < 8; od++) {
        int col = od*8 + c2;
        float v0 = oa[od][0]*i0, v1 = oa[od][1]*i0;
        float v2 = oa[od][2]*i1, v3 = oa[od][3]*i1;
        bf16 h0 = __float2bfloat16(v0), h1b = __float2bfloat16(v1);
        bf16 h2 = __float2bfloat16(v2), h3b = __float2bfloat16(v3);
        *(unsigned*)&g_o_h[t0 + col] = pack2(h0, h1b);
        *(unsigned*)&g_o_l[t0 + col] = packf2(v0 - __bfloat162float(h0), v1 - __bfloat162float(h1b));
        *(unsigned*)&g_o_h[t1 + col] = pack2(h2, h3b);
        *(unsigned*)&g_o_l[t1 + col] = packf2(v2 - __bfloat162float(h2), v3 - __bfloat162float(h3b));
    }
}

// ---------------- final rmsnorm: warp-per-row ----------------
__global__ void __launch_bounds__(256) final_rmsnorm_kernel(const float* __restrict__ fg,
                                                            float* __restrict__ out) {
    int row = blockIdx.x * 8 + (threadIdx.x >> 5);
    int lane = threadIdx.x & 31;
    const float* xr = g_x + (size_t)row * DIM;
    float4 v[4];
    float ss = 0.f;
    #pragma unroll
    for (int j = 0; j < 4; j++) {
        v[j] = *(const float4*)(xr + j*128 + lane*4);
        ss += v[j].x*v[j].x + v[j].y*v[j].y + v[j].z*v[j].z + v[j].w*v[j].w;
    }
    float n = sqrtf(warp_sum(ss));
    float sc = 22.62741699796952f / fmaxf(n, 1e-12f);
    float* outr = out + (size_t)row * DIM;
    #pragma unroll
    for (int j = 0; j < 4; j++) {
        float4 g4 = *(const float4*)(fg + j*128 + lane*4);
        float4 y;
        y.x = v[j].x * sc * (g4.x+1.f);
        y.y = v[j].y * sc * (g4.y+1.f);
        y.z = v[j].z * sc * (g4.z+1.f);
        y.w = v[j].w * sc * (g4.w+1.f);
        *(float4*)(outr + j*128 + lane*4) = y;
    }
}

// ---------------- host ----------------
extern "C" void kernel_launch(void* const* d_in, const int* in_sizes, int n_in,
                              void* d_out, int out_size) {
    const float* x          = (const float*)d_in[0];
    const float* times      = (const float*)d_in[1];
    const int* mod          = (const int*)d_in[3];
    const float* fourier_w  = (const float*)d_in[4];
    const float* time_w     = (const float*)d_in[5];
    const float* time_b     = (const float*)d_in[6];
    const float* aw_ln_g    = (const float*)d_in[7];
    const float* aw_scale   = (const float*)d_in[8];
    const float* aw_film_w  = (const float*)d_in[9];
    const float* aw_film_b  = (const float*)d_in[10];
    const float* aw_zero_w  = (const float*)d_in[11];
    const float* aw_zero_b  = (const float*)d_in[12];
    const float* attn_norm_g= (const float*)d_in[13];
    const float* qkv_w      = (const float*)d_in[14];
    const float* out_w      = (const float*)d_in[15];
    const float* fw_ln_g    = (const float*)d_in[16];
    const float* fw_scale   = (const float*)d_in[17];
    const float* fw_film_w  = (const float*)d_in[18];
    const float* fw_film_b  = (const float*)d_in[19];
    const float* fw_zero_w  = (const float*)d_in[20];
    const float* fw_zero_b  = (const float*)d_in[21];
    const float* ff_norm_g  = (const float*)d_in[22];
    const float* ff_w1      = (const float*)d_in[23];
    const float* ff_b1      = (const float*)d_in[24];
    const float* ff_w2      = (const float*)d_in[25];
    const float* ff_b2      = (const float*)d_in[26];
    const float* final_g    = (const float*)d_in[27];
    float* out = (float*)d_out;

    float *p_femb, *p_cond, *p_film, *p_gate, *p_x, *p_b1p, *p_sk;
    bf16 *p_xin_h, *p_xin_l, *p_o_h, *p_o_l, *p_act_h, *p_act_l;
    bf16 *p_wqkv_h, *p_wqkv_l, *p_wout_h, *p_wout_l, *p_wff1_h, *p_wff1_l, *p_wff2_h, *p_wff2_l;
    cudaGetSymbolAddress((void**)&p_femb, g_femb);
    cudaGetSymbolAddress((void**)&p_cond, g_cond);
    cudaGetSymbolAddress((void**)&p_film, g_film);
    cudaGetSymbolAddress((void**)&p_gate, g_gate);
    cudaGetSymbolAddress((void**)&p_x,    g_x);
    cudaGetSymbolAddress((void**)&p_b1p,  g_b1p);
    cudaGetSymbolAddress((void**)&p_sk,   g_sk);
    cudaGetSymbolAddress((void**)&p_xin_h, g_xin_h);
    cudaGetSymbolAddress((void**)&p_xin_l, g_xin_l);
    cudaGetSymbolAddress((void**)&p_o_h,   g_o_h);
    cudaGetSymbolAddress((void**)&p_o_l,   g_o_l);
    cudaGetSymbolAddress((void**)&p_act_h, g_act_h);
    cudaGetSymbolAddress((void**)&p_act_l, g_act_l);
    cudaGetSymbolAddress((void**)&p_wqkv_h, g_wqkv_h);
    cudaGetSymbolAddress((void**)&p_wqkv_l, g_wqkv_l);
    cudaGetSymbolAddress((void**)&p_wout_h, g_wout_h);
    cudaGetSymbolAddress((void**)&p_wout_l, g_wout_l);
    cudaGetSymbolAddress((void**)&p_wff1_h, g_wff1_h);
    cudaGetSymbolAddress((void**)&p_wff1_l, g_wff1_l);
    cudaGetSymbolAddress((void**)&p_wff2_h, g_wff2_h);
    cudaGetSymbolAddress((void**)&p_wff2_l, g_wff2_l);

    static bool attr_set = false;
    if (!attr_set) {
        cudaFuncSetAttribute(mma_gemm_kernel,
                             cudaFuncAttributeMaxDynamicSharedMemorySize, GEMM_SMEM);
        cudaFuncSetAttribute(flash_mma_kernel,
                             cudaFuncAttributeMaxDynamicSharedMemorySize, FLASH_SMEM);
        attr_set = true;
    }

    copy_x_kernel<<<(NT*DIM + 255)/256, 256>>>(x);

    {
        int n1 = NL*DIM*3*DIM/4;
        split_kernel<<<(n1+255)/256, 256>>>(qkv_w, p_wqkv_h, p_wqkv_l, n1);
        int n2 = NL*DIM*DIM/4;
        split_kernel<<<(n2+255)/256, 256>>>(out_w, p_wout_h, p_wout_l, n2);
        size_t n3 = (size_t)NL*DIM*2*FFIP/4;
        split_ff1_kernel<<<(unsigned)((n3+255)/256), 256>>>(ff_w1);
        size_t n4 = (size_t)NL*FFIP*DIM/4;
        split_ff2_kernel<<<(unsigned)((n4+255)/256), 256>>>(ff_w2);
        pad_b1_kernel<<<(NL*2*FFIP+255)/256, 256>>>(ff_b1);
    }

    femb_kernel<<<(BB*(DIM+1) + 255)/256, 256>>>(times, fourier_w);
    cond_mm_kernel<<<dim3(DC/128, BB*4, 1), 128>>>(p_femb, time_w, DC, DIM+1, 129, 4);
    cond_reduce_kernel<<<(BB*DC+255)/256, 256>>>(time_b, p_cond, DC, 4, 1);

    cond_mm2_kernel<<<dim3((2*DIM)/128, BB*8, 2*NL), 128>>>(
        p_cond, aw_film_w, fw_film_w, 2*DIM, DC, 256, 8);
    cond_reduce2_kernel<<<(2*NL*BB*2*DIM+255)/256, 256>>>(
        aw_film_b, fw_film_b, p_film, 2*DIM, 8, 0);
    cond_mm2_kernel<<<dim3(DIM/128, BB*8, 2*NL), 128>>>(
        p_cond, aw_zero_w, fw_zero_w, DIM, DC, 256, 8);
    cond_reduce2_kernel<<<(2*NL*BB*DIM+255)/256, 256>>>(
        aw_zero_b, fw_zero_b, p_gate, DIM, 8, 2);

    for (int l = 0; l < NL; l++) {
        // ---- attention branch ----
        modulate_kernel<<<NT/8, 256>>>(p_x, p_xin_h, p_xin_l,
            p_film + ((size_t)(0*NL + l))*BB*2*DIM,
            aw_ln_g + (size_t)l*DIM, attn_norm_g + (size_t)l*DIM, mod);
        mma_gemm_kernel<<<dim3((3*DIM)/128, NT/128), 256, GEMM_SMEM>>>(
            p_xin_h, p_xin_l,
            p_wqkv_h + (size_t)l*DIM*3*DIM, p_wqkv_l + (size_t)l*DIM*3*DIM,
            nullptr, nullptr, NT, 3*DIM, DIM, 1, nullptr, nullptr, nullptr);
        flash_mma_kernel<<<dim3(SS/64, NH, BB), 128, FLASH_SMEM>>>();
        mma_gemm_kernel<<<dim3(DIM/128, NT/128, 2), 256, GEMM_SMEM>>>(
            p_o_h, p_o_l,
            p_wout_h + (size_t)l*DIM*DIM, p_wout_l + (size_t)l*DIM*DIM,
            nullptr, p_sk, NT, DIM, DIM, 4, nullptr, nullptr, nullptr);
        skres_kernel<<<(NT*DIM/4 + 255)/256, 256>>>(
            nullptr, p_gate + ((size_t)(0*NL + l))*BB*DIM, aw_scale + (size_t)l*DIM, mod);

        // ---- feedforward branch ----
        modulate_kernel<<<NT/8, 256>>>(p_x, p_xin_h, p_xin_l,
            p_film + ((size_t)(1*NL + l))*BB*2*DIM,
            fw_ln_g + (size_t)l*DIM, ff_norm_g + (size_t)l*DIM, mod);
        mma_gemm_kernel<<<dim3((2*FFIP)/128, NT/128), 256, GEMM_SMEM>>>(
            p_xin_h, p_xin_l,
            p_wff1_h + (size_t)l*DIM*2*FFIP, p_wff1_l + (size_t)l*DIM*2*FFIP,
            p_b1p + (size_t)l*2*FFIP, nullptr, NT, 2*FFIP, DIM, 3, nullptr, nullptr, nullptr);
        mma_gemm_kernel<<<dim3(DIM/128, NT/128, 2), 256, GEMM_SMEM>>>(
            p_act_h, p_act_l,
            p_wff2_h + (size_t)l*FFIP*DIM, p_wff2_l + (size_t)l*FFIP*DIM,
            nullptr, p_sk, NT, DIM, FFIP, 4, nullptr, nullptr, nullptr);
        skres_kernel<<<(NT*DIM/4 + 255)/256, 256>>>(
            ff_b2 + (size_t)l*DIM, p_gate + ((size_t)(1*NL + l))*BB*DIM,
            fw_scale + (size_t)l*DIM, mod);
    }

    final_rmsnorm_kernel<<<NT/8, 256>>>(final_g, out);
}

// round 17
// speedup vs baseline: 1.1037x; 1.0176x over previous
#include <cuda_runtime.h>
#include <cuda_bf16.h>
#include <math.h>

#define BB 2
#define SS 2048
#define DIM 512
#define NT (BB*SS)
#define NH 8
#define DH 64
#define DC 2048
#define FFI 1365
#define FFIP 1408
#define NL 4

typedef __nv_bfloat16 bf16;

// ---------------- scratch (static device globals; no allocation) ----------------
__device__ float g_x[NT*DIM];
__device__ float g_femb[BB*(DIM+1)];
__device__ float g_cond[BB*DC];
__device__ float g_film[2*NL*BB*2*DIM];
__device__ float g_gate[2*NL*BB*DIM];
__device__ float g_b1p[NL*2*FFIP];
__device__ float g_part[8*2*NL*BB*2*DIM];
__device__ float g_sk[2][NT*DIM];          // split-K partials

// split-precision activation buffers
__device__ __align__(128) bf16 g_xin_h[NT*DIM],  g_xin_l[NT*DIM];
__device__ __align__(128) bf16 g_o_h[NT*DIM],    g_o_l[NT*DIM];
__device__ __align__(128) bf16 g_act_h[(size_t)NT*FFIP], g_act_l[(size_t)NT*FFIP];
// attention operands, [b][h][s][64] layout
__device__ __align__(128) bf16 g_q_h[NT*DIM], g_q_l[NT*DIM];
__device__ __align__(128) bf16 g_k_h[NT*DIM], g_k_l[NT*DIM];
__device__ __align__(128) bf16 g_v_h[NT*DIM], g_v_l[NT*DIM];
// split-precision weights (ff1 INTERLEAVED a/g columns; ff1/ff2 padded)
__device__ __align__(128) bf16 g_wqkv_h[NL*DIM*3*DIM], g_wqkv_l[NL*DIM*3*DIM];
__device__ __align__(128) bf16 g_wout_h[NL*DIM*DIM],   g_wout_l[NL*DIM*DIM];
__device__ __align__(128) bf16 g_wff1_h[(size_t)NL*DIM*2*FFIP], g_wff1_l[(size_t)NL*DIM*2*FFIP];
__device__ __align__(128) bf16 g_wff2_h[(size_t)NL*FFIP*DIM],   g_wff2_l[(size_t)NL*FFIP*DIM];

// ---------------- helpers ----------------
__device__ __forceinline__ void wsplit(float v, bf16* h, bf16* l, size_t idx) {
    bf16 hi = __float2bfloat16(v);
    h[idx] = hi;
    l[idx] = __float2bfloat16(v - __bfloat162float(hi));
}
__device__ __forceinline__ unsigned pack2(bf16 a, bf16 b) {
    unsigned short ua = *(unsigned short*)&a, ub = *(unsigned short*)&b;
    return (unsigned)ua | ((unsigned)ub << 16);
}
__device__ __forceinline__ unsigned packf2(float a, float b) {
    return pack2(__float2bfloat16(a), __float2bfloat16(b));
}
__device__ __forceinline__ void split4(float4 v, uint2& H, uint2& L) {
    bf16 h0 = __float2bfloat16(v.x), h1 = __float2bfloat16(v.y);
    bf16 h2 = __float2bfloat16(v.z), h3 = __float2bfloat16(v.w);
    H = make_uint2(pack2(h0, h1), pack2(h2, h3));
    L = make_uint2(packf2(v.x - __bfloat162float(h0), v.y - __bfloat162float(h1)),
                   packf2(v.z - __bfloat162float(h2), v.w - __bfloat162float(h3)));
}
__device__ __forceinline__ float tanh_ap(float x) {
    float y; asm("tanh.approx.f32 %0, %1;" : "=f"(y) : "f"(x)); return y;
}
__device__ __forceinline__ float warp_sum(float v) {
    #pragma unroll
    for (int o = 16; o > 0; o >>= 1) v += __shfl_xor_sync(0xffffffffu, v, o);
    return v;
}

__device__ __forceinline__ void mma16816(float* d, const unsigned* a, const unsigned* b) {
    asm volatile(
        "mma.sync.aligned.m16n8k16.row.col.f32.bf16.bf16.f32 "
        "{%0,%1,%2,%3}, {%4,%5,%6,%7}, {%8,%9}, {%0,%1,%2,%3};"
        : "+f"(d[0]), "+f"(d[1]), "+f"(d[2]), "+f"(d[3])
        : "r"(a[0]), "r"(a[1]), "r"(a[2]), "r"(a[3]), "r"(b[0]), "r"(b[1]));
}

#define LDSM_X4(r0,r1,r2,r3,addr) \
    asm volatile("ldmatrix.sync.aligned.m8n8.x4.shared.b16 {%0,%1,%2,%3}, [%4];" \
        : "=r"(r0),"=r"(r1),"=r"(r2),"=r"(r3) : "r"(addr))
#define LDSM_X4T(r0,r1,r2,r3,addr) \
    asm volatile("ldmatrix.sync.aligned.m8n8.x4.trans.shared.b16 {%0,%1,%2,%3}, [%4];" \
        : "=r"(r0),"=r"(r1),"=r"(r2),"=r"(r3) : "r"(addr))

__device__ __forceinline__ void cpa16(void* dst, const void* src) {
    unsigned d = (unsigned)__cvta_generic_to_shared(dst);
    asm volatile("cp.async.cg.shared.global [%0], [%1], 16;"
                 :: "r"(d), "l"(src) : "memory");
}
template<int W> __device__ __forceinline__ void cpwait() {
    asm volatile("cp.async.wait_group %0;" :: "n"(W) : "memory");
}
__device__ __forceinline__ void cpcommit() {
    asm volatile("cp.async.commit_group;" ::: "memory");
}

// ---------------- small kernels ----------------
__global__ void copy_x_kernel(const float* __restrict__ x) {
    int i = blockIdx.x * 256 + threadIdx.x;
    if (i < NT*DIM) g_x[i] = x[i];
}

__global__ void split_kernel(const float* __restrict__ s, bf16* __restrict__ h,
                             bf16* __restrict__ l, int n4) {
    int i = blockIdx.x * 256 + threadIdx.x;
    if (i >= n4) return;
    float4 v = ((const float4*)s)[i];
    uint2 H, L;
    split4(v, H, L);
    ((uint2*)h)[i] = H;
    ((uint2*)l)[i] = L;
}

// ff1 weights interleaved: out col 2c = a_c (src col c), 2c+1 = g_c (src col FFI+c)
__global__ void split_ff1_kernel(const float* __restrict__ s) {
    size_t i4 = (size_t)blockIdx.x * 256 + threadIdx.x;
    size_t total4 = (size_t)NL * DIM * 2 * FFIP / 4;
    if (i4 >= total4) return;
    size_t i = i4 * 4;
    int col = (int)(i % (2*FFIP));
    size_t rowg = i / (2*FFIP);
    const float* sr = s + rowg * (2*FFI);
    int c0 = col >> 1;
    float a0 = (c0 < FFI)   ? sr[c0]       : 0.f;
    float g0 = (c0 < FFI)   ? sr[FFI+c0]   : 0.f;
    float a1 = (c0+1 < FFI) ? sr[c0+1]     : 0.f;
    float g1 = (c0+1 < FFI) ? sr[FFI+c0+1] : 0.f;
    uint2 H, L;
    split4(make_float4(a0, g0, a1, g1), H, L);
    ((uint2*)g_wff1_h)[i4] = H;
    ((uint2*)g_wff1_l)[i4] = L;
}

__global__ void split_ff2_kernel(const float* __restrict__ s) {
    size_t i4 = (size_t)blockIdx.x * 256 + threadIdx.x;
    size_t total4 = (size_t)NL * FFIP * DIM / 4;
    if (i4 >= total4) return;
    size_t i = i4 * 4;
    int col = (int)(i % DIM);
    size_t rowg = i / DIM;
    int l = (int)(rowg / FFIP);
    int row = (int)(rowg % FFIP);
    float4 v = make_float4(0.f, 0.f, 0.f, 0.f);
    if (row < FFI) v = *(const float4*)(s + ((size_t)l*FFI + row) * DIM + col);
    uint2 H, L;
    split4(v, H, L);
    ((uint2*)g_wff2_h)[i4] = H;
    ((uint2*)g_wff2_l)[i4] = L;
}

__global__ void pad_b1_kernel(const float* __restrict__ s) {
    int i = blockIdx.x * 256 + threadIdx.x;
    if (i >= NL*2*FFIP) return;
    int col = i % (2*FFIP);
    int l = i / (2*FFIP);
    int c = col >> 1;
    float v = 0.f;
    if (c < FFI) v = s[l*(2*FFI) + ((col & 1) ? FFI : 0) + c];
    g_b1p[i] = v;
}

__global__ void femb_kernel(const float* __restrict__ times, const float* __restrict__ fw) {
    int i = blockIdx.x * blockDim.x + threadIdx.x;
    if (i >= BB*(DIM+1)) return;
    int b = i / (DIM+1), c = i % (DIM+1);
    float t = times[b];
    float v;
    if (c == 0) v = t;
    else if (c <= DIM/2) v = sinf(t * fw[c-1] * 6.283185307179586f);
    else v = cosf(t * fw[c-1-DIM/2] * 6.283185307179586f);
    g_femb[i] = v;
}

// ---------------- conditioning GEMMs ----------------
__global__ void cond_mm_kernel(const float* __restrict__ A, const float* __restrict__ W,
                               int N, int K, int kchunk, int KS) {
    int n = blockIdx.x * 128 + threadIdx.x;
    int m = blockIdx.y / KS, kc = blockIdx.y % KS;
    int k0 = kc * kchunk;
    int k1 = k0 + kchunk; if (k1 > K) k1 = K;
    const float* a = A + (size_t)m*K;
    float s = 0.f;
    #pragma unroll 4
    for (int k = k0; k < k1; k++) s += a[k] * __ldg(&W[(size_t)k*N + n]);
    g_part[((size_t)kc*BB + m)*N + n] = s;
}

__global__ void cond_reduce_kernel(const float* __restrict__ bias, float* __restrict__ out,
                                   int N, int KS, int act) {
    int i = blockIdx.x*256 + threadIdx.x;
    if (i >= BB*N) return;
    int n = i % N;
    int m = i / N;
    float s = bias[n];
    for (int kc = 0; kc < KS; kc++)
        s += g_part[((size_t)kc*BB + m)*N + n];
    if (act == 1) s = s / (1.f + expf(-s));
    out[i] = s;
}

// merged both-branch film/gate GEMMs: z in [0, 2*NL), br = z/NL, l = z%NL
__global__ void cond_mm2_kernel(const float* __restrict__ A,
                                const float* __restrict__ W0, const float* __restrict__ W1,
                                int N, int K, int kchunk, int KS) {
    int n = blockIdx.x * 128 + threadIdx.x;
    int m = blockIdx.y / KS, kc = blockIdx.y % KS;
    int z = blockIdx.z;
    int br = z / NL, l = z % NL;
    const float* w = (br ? W1 : W0) + (size_t)l*K*N;
    int k0 = kc * kchunk;
    int k1 = k0 + kchunk; if (k1 > K) k1 = K;
    const float* a = A + (size_t)m*K;
    float s = 0.f;
    #pragma unroll 4
    for (int k = k0; k < k1; k++) s += a[k] * __ldg(&w[(size_t)k*N + n]);
    g_part[(((size_t)kc*(2*NL) + z)*BB + m)*N + n] = s;
}

__global__ void cond_reduce2_kernel(const float* __restrict__ b0, const float* __restrict__ b1,
                                    float* __restrict__ out, int N, int KS, int act) {
    int i = blockIdx.x*256 + threadIdx.x;
    if (i >= 2*NL*BB*N) return;
    int z = i / (BB*N);
    int n = i % N;
    int m = (i / N) % BB;
    const float* bias = (z < NL) ? b0 + (size_t)z*N : b1 + (size_t)(z-NL)*N;
    float s = bias[n];
    for (int kc = 0; kc < KS; kc++)
        s += g_part[(((size_t)kc*(2*NL) + z)*BB + m)*N + n];
    if (act == 2) s = 1.f / (1.f + expf(-s));
    out[i] = s;
}

// ---------------- modulate: warp-per-row, fused split-K residual prologue ----------------
// has_res: add (sk0+sk1+rbias)*gatesel to x first (the previous branch's residual),
// write updated x back to g_x, then layernorm->FiLM->rmsnorm->split-bf16 as before.
__global__ void __launch_bounds__(256) modulate_kernel(float* __restrict__ xbuf,
                                bf16* __restrict__ dh, bf16* __restrict__ dl,
                                const float* __restrict__ film,
                                const float* __restrict__ ln_g,
                                const float* __restrict__ norm_g,
                                const int* __restrict__ mod,
                                const float* __restrict__ rbias,
                                const float* __restrict__ rgate,
                                const float* __restrict__ rlscale,
                                int has_res) {
    int row = blockIdx.x * 8 + (threadIdx.x >> 5);
    int lane = threadIdx.x & 31;
    int b = row / SS;
    bool m = mod[row] != 0;
    float* xr = xbuf + (size_t)row * DIM;

    float4 v[4];
    float s = 0.f;
    #pragma unroll
    for (int j = 0; j < 4; j++) {
        v[j] = *(const float4*)(xr + j*128 + lane*4);
        if (has_res) {
            int i4 = row*128 + j*32 + lane;
            float4 s0 = ((const float4*)g_sk[0])[i4];
            float4 s1 = ((const float4*)g_sk[1])[i4];
            int c = j*128 + lane*4;
            float4 bb = rbias ? *(const float4*)(rbias + c) : make_float4(0.f,0.f,0.f,0.f);
            const float* gsrc = m ? (rgate + b*DIM) : rlscale;
            float4 g4 = *(const float4*)(gsrc + c);
            v[j].x += (s0.x + s1.x + bb.x) * g4.x;
            v[j].y += (s0.y + s1.y + bb.y) * g4.y;
            v[j].z += (s0.z + s1.z + bb.z) * g4.z;
            v[j].w += (s0.w + s1.w + bb.w) * g4.w;
            *(float4*)(xr + j*128 + lane*4) = v[j];
        }
        s += v[j].x + v[j].y + v[j].z + v[j].w;
    }
    float mean = warp_sum(s) * (1.f/DIM);
    float vv = 0.f;
    #pragma unroll
    for (int j = 0; j < 4; j++) {
        float d0 = v[j].x-mean, d1 = v[j].y-mean, d2 = v[j].z-mean, d3 = v[j].w-mean;
        vv += d0*d0 + d1*d1 + d2*d2 + d3*d3;
    }
    float rstd = rsqrtf(warp_sum(vv) * (1.f/DIM) + 1e-5f);

    float4 xmod[4];
    float ss = 0.f;
    #pragma unroll
    for (int j = 0; j < 4; j++) {
        float4 g4, b4;
        if (m) {
            const float* f = film + (size_t)b * 2 * DIM;
            g4 = *(const float4*)(f + j*128 + lane*4);
            b4 = *(const float4*)(f + DIM + j*128 + lane*4);
        } else {
            g4 = *(const float4*)(ln_g + j*128 + lane*4);
            b4 = make_float4(0.f, 0.f, 0.f, 0.f);
        }
        xmod[j].x = (v[j].x-mean)*rstd*(g4.x+1.f) + b4.x;
        xmod[j].y = (v[j].y-mean)*rstd*(g4.y+1.f) + b4.y;
        xmod[j].z = (v[j].z-mean)*rstd*(g4.z+1.f) + b4.z;
        xmod[j].w = (v[j].w-mean)*rstd*(g4.w+1.f) + b4.w;
        ss += xmod[j].x*xmod[j].x + xmod[j].y*xmod[j].y
            + xmod[j].z*xmod[j].z + xmod[j].w*xmod[j].w;
    }
    float n = sqrtf(warp_sum(ss));
    float sc = 22.62741699796952f / fmaxf(n, 1e-12f);

    size_t base = (size_t)row * DIM;
    #pragma unroll
    for (int j = 0; j < 4; j++) {
        float4 n4 = *(const float4*)(norm_g + j*128 + lane*4);
        float4 y;
        y.x = xmod[j].x * sc * (n4.x+1.f);
        y.y = xmod[j].y * sc * (n4.y+1.f);
        y.z = xmod[j].z * sc * (n4.z+1.f);
        y.w = xmod[j].w * sc * (n4.w+1.f);
        uint2 H, L;
        split4(y, H, L);
        *(uint2*)&dh[base + j*128 + lane*4] = H;
        *(uint2*)&dl[base + j*128 + lane*4] = L;
    }
}

// ---------------- tensor-core split-bf16 GEMM, cp.async 2-stage pipeline ----------------
// modes: 0 = C (+bias) fp32; 1 = qkv split write; 2 = gated residual into g_x;
//        3 = interleaved GEGLU -> split g_act; 4 = split-K partial (C + z*M*N)
#define LDA 40
#define LDB 136
#define STG 18944
#define GEMM_SMEM (2*STG*2)

__device__ __forceinline__ void gemm_issue(bf16* st, const bf16* Ah, const bf16* Al,
        const bf16* Bh, const bf16* Bl, int bm, int bn, int N, int K, int k0, int tid) {
    #pragma unroll
    for (int hl = 0; hl < 2; hl++) {
        const bf16* a = hl ? Al : Ah;
        bf16* as = st + hl*5120;
        #pragma unroll
        for (int i = 0; i < 2; i++) {
            int ch = i*256 + tid;
            int row = ch >> 2, kc = (ch & 3)*8;
            cpa16(as + row*LDA + kc, a + (size_t)(bm+row)*K + k0 + kc);
        }
        const bf16* b = hl ? Bl : Bh;
        bf16* bs = st + 10240 + hl*4352;
        #pragma unroll
        for (int i = 0; i < 2; i++) {
            int ch = i*256 + tid;
            int kr = ch >> 4, nc = (ch & 15)*8;
            cpa16(bs + kr*LDB + nc, b + (size_t)(k0+kr)*N + bn + nc);
        }
    }
    cpcommit();
}

__global__ void __launch_bounds__(256) mma_gemm_kernel(
        const bf16* __restrict__ Ah, const bf16* __restrict__ Al,
        const bf16* __restrict__ Bh, const bf16* __restrict__ Bl,
        const float* __restrict__ bias, float* __restrict__ C,
        int M, int N, int K, int mode,
        const float* __restrict__ gate, const float* __restrict__ lscale,
        const int* __restrict__ mod) {
    extern __shared__ __align__(16) bf16 dsm[];
    int tid = threadIdx.x, lane = tid & 31, wid = tid >> 5;
    int bm = blockIdx.y * 128, bn = blockIdx.x * 128;
    int mf = (wid >> 1) * 32, nf = (wid & 1) * 64;

    int kspan = K / (int)gridDim.z;
    int kbase = (int)blockIdx.z * kspan;

    float acc[2][8][4];
    #pragma unroll
    for (int i = 0; i < 2; i++)
        #pragma unroll
        for (int j = 0; j < 8; j++)
            #pragma unroll
            for (int r = 0; r < 4; r++) acc[i][j][r] = 0.f;

    int a_m = mf + (lane & 7) + ((lane >> 3) & 1) * 8;
    int a_k = (lane >> 4) * 8;
    int b_k = (lane & 7) + ((lane >> 3) & 1) * 8;
    int b_n = nf + (lane >> 4) * 8;

    int niter = kspan >> 5;
    gemm_issue(dsm, Ah, Al, Bh, Bl, bm, bn, N, K, kbase, tid);

    for (int it = 0; it < niter; it++) {
        if (it + 1 < niter) {
            gemm_issue(dsm + ((it+1) & 1)*STG, Ah, Al, Bh, Bl, bm, bn, N, K,
                       kbase + ((it+1) << 5), tid);
            cpwait<1>();
        } else {
            cpwait<0>();
        }
        __syncthreads();
        bf16* As0 = dsm + (it & 1)*STG;
        bf16* As1 = As0 + 5120;
        bf16* Bs0 = As0 + 10240;
        bf16* Bs1 = Bs0 + 4352;

        #pragma unroll
        for (int kk = 0; kk < 32; kk += 16) {
            unsigned af[2][2][4];
            #pragma unroll
            for (int hl = 0; hl < 2; hl++) {
                bf16* as = hl ? As1 : As0;
                #pragma unroll
                for (int mi = 0; mi < 2; mi++) {
                    unsigned sa = (unsigned)__cvta_generic_to_shared(
                        &as[(a_m + mi*16)*LDA + kk + a_k]);
                    LDSM_X4(af[hl][mi][0], af[hl][mi][1], af[hl][mi][2], af[hl][mi][3], sa);
                }
            }
            unsigned bfr[2][8][2];
            #pragma unroll
            for (int hl = 0; hl < 2; hl++) {
                bf16* bs = hl ? Bs1 : Bs0;
                #pragma unroll
                for (int np = 0; np < 4; np++) {
                    unsigned sa = (unsigned)__cvta_generic_to_shared(
                        &bs[(kk + b_k)*LDB + b_n + np*16]);
                    unsigned r0, r1, r2, r3;
                    LDSM_X4T(r0, r1, r2, r3, sa);
                    bfr[hl][np*2][0]   = r0; bfr[hl][np*2][1]   = r1;
                    bfr[hl][np*2+1][0] = r2; bfr[hl][np*2+1][1] = r3;
                }
            }
            #pragma unroll
            for (int mi = 0; mi < 2; mi++)
                #pragma unroll
                for (int nj = 0; nj < 8; nj++) {
                    mma16816(acc[mi][nj], af[0][mi], bfr[0][nj]);
                    mma16816(acc[mi][nj], af[0][mi], bfr[1][nj]);
                    mma16816(acc[mi][nj], af[1][mi], bfr[0][nj]);
                }
        }
        __syncthreads();
    }

    // ---- epilogue ----
    if (mode == 0) {
        #pragma unroll
        for (int mi = 0; mi < 2; mi++) {
            int r0 = bm + mf + mi*16 + (lane >> 2);
            #pragma unroll
            for (int nj = 0; nj < 8; nj++) {
                int c0 = bn + nf + nj*8 + (lane & 3)*2;
                float b0 = bias ? bias[c0] : 0.f;
                float b1 = bias ? bias[c0+1] : 0.f;
                C[(size_t)r0*N + c0]       = acc[mi][nj][0] + b0;
                C[(size_t)(r0+8)*N + c0]   = acc[mi][nj][2] + b0;
                C[(size_t)r0*N + c0+1]     = acc[mi][nj][1] + b1;
                C[(size_t)(r0+8)*N + c0+1] = acc[mi][nj][3] + b1;
            }
        }
    } else if (mode == 1) {
        #pragma unroll
        for (int mi = 0; mi < 2; mi++) {
            int m0 = bm + mf + mi*16 + (lane >> 2);
            #pragma unroll
            for (int nj = 0; nj < 8; nj++) {
                int c0 = bn + nf + nj*8 + (lane & 3)*2;
                int c3 = c0 >> 9;
                int hh = (c0 & 511) >> 6;
                int d  = c0 & 63;
                float sc = (c3 == 0) ? 0.125f : 1.f;
                bf16* H = (c3 == 0) ? g_q_h : (c3 == 1 ? g_k_h : g_v_h);
                bf16* L = (c3 == 0) ? g_q_l : (c3 == 1 ? g_k_l : g_v_l);
                #pragma unroll
                for (int rr = 0; rr < 2; rr++) {
                    int m = m0 + rr*8;
                    float v0 = acc[mi][nj][rr*2]   * sc;
                    float v1 = acc[mi][nj][rr*2+1] * sc;
                    size_t o = ((size_t)((m/SS)*NH + hh)*SS + (m % SS))*DH + d;
                    bf16 h0 = __float2bfloat16(v0), h1 = __float2bfloat16(v1);
                    *(unsigned*)&H[o] = pack2(h0, h1);
                    *(unsigned*)&L[o] = packf2(v0 - __bfloat162float(h0),
                                               v1 - __bfloat162float(h1));
                }
            }
        }
    } else if (mode == 2) {
        #pragma unroll
        for (int mi = 0; mi < 2; mi++) {
            int m0 = bm + mf + mi*16 + (lane >> 2);
            #pragma unroll
            for (int nj = 0; nj < 8; nj++) {
                int c0 = bn + nf + nj*8 + (lane & 3)*2;
                #pragma unroll
                for (int rr = 0; rr < 2; rr++) {
                    int m = m0 + rr*8;
                    bool mm = mod[m] != 0;
                    int bidx = m / SS;
                    #pragma unroll
                    for (int e = 0; e < 2; e++) {
                        int c = c0 + e;
                        float v = acc[mi][nj][rr*2 + e];
                        if (bias) v += bias[c];
                        float r = mm ? v * gate[bidx*DIM + c] : v * lscale[c];
                        g_x[(size_t)m*DIM + c] += r;
                    }
                }
            }
        }
    } else if (mode == 3) {
        // interleaved GEGLU epilogue -> split bf16 g_act
        #pragma unroll
        for (int mi = 0; mi < 2; mi++) {
            int m0 = bm + mf + mi*16 + (lane >> 2);
            #pragma unroll
            for (int nj = 0; nj < 8; nj++) {
                int c0 = bn + nf + nj*8 + (lane & 3)*2;
                int cc = c0 >> 1;
                float ba = bias[c0], bg = bias[c0+1];
                #pragma unroll
                for (int rr = 0; rr < 2; rr++) {
                    int m = m0 + rr*8;
                    float a = acc[mi][nj][rr*2]   + ba;
                    float g = acc[mi][nj][rr*2+1] + bg;
                    float ge = 0.5f * g * (1.f + erff(g * 0.7071067811865475f));
                    wsplit(ge * a, g_act_h, g_act_l, (size_t)m*FFIP + cc);
                }
            }
        }
    } else {
        // mode 4: split-K partial write
        float* dst = C + (size_t)blockIdx.z * ((size_t)M * N);
        #pragma unroll
        for (int mi = 0; mi < 2; mi++) {
            int r0 = bm + mf + mi*16 + (lane >> 2);
            #pragma unroll
            for (int nj = 0; nj < 8; nj++) {
                int c0 = bn + nf + nj*8 + (lane & 3)*2;
                dst[(size_t)r0*N + c0]       = acc[mi][nj][0];
                dst[(size_t)(r0+8)*N + c0]   = acc[mi][nj][2];
                dst[(size_t)r0*N + c0+1]     = acc[mi][nj][1];
                dst[(size_t)(r0+8)*N + c0+1] = acc[mi][nj][3];
            }
        }
    }
}

// ---------------- tensor-core flash attention ----------------
// 128 threads, 64 q-rows/block, 64-key tiles, cp.async double-buffered. FIFO order.
#define FP 72
#define FSTG (4*64*FP)
#define FLASH_SMEM (2*FSTG*2)

__device__ __forceinline__ void flash_issue(bf16* st, size_t base, int jt, int tid) {
    #pragma unroll
    for (int i2 = 0; i2 < 4; i2++) {
        int e = i2*128 + tid;
        int key = e >> 3, dg = (e & 7) * 8;
        size_t g = base + (size_t)(jt + key)*DH + dg;
        int so = key*FP + dg;
        cpa16(st + so,         g_k_h + g);
        cpa16(st + 4608 + so,  g_k_l + g);
        cpa16(st + 9216 + so,  g_v_h + g);
        cpa16(st + 13824 + so, g_v_l + g);
    }
    cpcommit();
}

__global__ void __launch_bounds__(128) flash_mma_kernel() {
    extern __shared__ __align__(16) bf16 fsm[];
    int tid = threadIdx.x, lane = tid & 31, w = tid >> 5;
    int q0 = blockIdx.x * 64;
    int h = blockIdx.y, b = blockIdx.z;
    size_t base = ((size_t)(b*NH + h))*SS*DH;
    int r = lane >> 2, c2 = (lane & 3) * 2;
    int qr0 = q0 + w*16 + r;

    unsigned qf[2][4][4];
    #pragma unroll
    for (int kt = 0; kt < 4; kt++) {
        size_t p0 = base + (size_t)qr0*DH + kt*16 + c2;
        size_t p1 = base + (size_t)(qr0+8)*DH + kt*16 + c2;
        qf[0][kt][0] = *(const unsigned*)(g_q_h + p0);
        qf[0][kt][1] = *(const unsigned*)(g_q_h + p1);
        qf[0][kt][2] = *(const unsigned*)(g_q_h + p0 + 8);
        qf[0][kt][3] = *(const unsigned*)(g_q_h + p1 + 8);
        qf[1][kt][0] = *(const unsigned*)(g_q_l + p0);
        qf[1][kt][1] = *(const unsigned*)(g_q_l + p1);
        qf[1][kt][2] = *(const unsigned*)(g_q_l + p0 + 8);
        qf[1][kt][3] = *(const unsigned*)(g_q_l + p1 + 8);
    }

    float oa[8][4];
    #pragma unroll
    for (int i = 0; i < 8; i++)
        #pragma unroll
        for (int e = 0; e < 4; e++) oa[i][e] = 0.f;
    float m0 = -1e30f, m1 = -1e30f, l0 = 0.f, l1 = 0.f;

    int klg = lane >> 3, klr = lane & 7;
    int kkey = (klg >> 1) * 8 + klr;
    int kd8 = (klg & 1) * 8;
    int vbk = (lane & 7) + ((lane >> 3) & 1) * 8;
    int vbn = (lane >> 4) * 8;

    int nt = (q0 >> 6) + 1;
    flash_issue(fsm, base, 0, tid);

    for (int it = 0; it < nt; it++) {
        int jt = it << 6;
        if (it + 1 < nt) {
            flash_issue(fsm + ((it+1) & 1)*FSTG, base, jt + 64, tid);
            cpwait<1>();
        } else {
            cpwait<0>();
        }
        __syncthreads();
        bf16* Ksh = fsm + (it & 1)*FSTG;
        bf16* Ksl = Ksh + 4608;
        bf16* Vsh = Ksh + 9216;
        bf16* Vsl = Ksh + 13824;

        float sa[8][4];
        #pragma unroll
        for (int njp = 0; njp < 4; njp++) {
            #pragma unroll
            for (int e = 0; e < 4; e++) { sa[njp*2][e] = 0.f; sa[njp*2+1][e] = 0.f; }
            #pragma unroll
            for (int kt = 0; kt < 4; kt++) {
                unsigned kh0,kh1,kh2,kh3, kl0,kl1,kl2,kl3;
                unsigned ah = (unsigned)__cvta_generic_to_shared(
                    &Ksh[(njp*16 + kkey)*FP + kt*16 + kd8]);
                unsigned al = (unsigned)__cvta_generic_to_shared(
                    &Ksl[(njp*16 + kkey)*FP + kt*16 + kd8]);
                LDSM_X4(kh0, kh1, kh2, kh3, ah);
                LDSM_X4(kl0, kl1, kl2, kl3, al);
                unsigned bh0[2] = {kh0,kh1}, bh1[2] = {kh2,kh3};
                unsigned bl0[2] = {kl0,kl1}, bl1[2] = {kl2,kl3};
                mma16816(sa[njp*2],   qf[0][kt], bh0);
                mma16816(sa[njp*2],   qf[0][kt], bl0);
                mma16816(sa[njp*2],   qf[1][kt], bh0);
                mma16816(sa[njp*2+1], qf[0][kt], bh1);
                mma16816(sa[njp*2+1], qf[0][kt], bl1);
                mma16816(sa[njp*2+1], qf[1][kt], bh1);
            }
        }

        bool diag = (jt == q0);
        float mx0 = -1e30f, mx1 = -1e30f;
        #pragma unroll
        for (int nj = 0; nj < 8; nj++) {
            #pragma unroll
            for (int e = 0; e < 4; e++) {
                float s = 50.f * tanh_ap(sa[nj][e] * 0.02f);
                if (diag) {
                    int jc = jt + nj*8 + c2 + (e & 1);
                    int qr = qr0 + ((e >> 1) ? 8 : 0);
                    if (jc > qr) s = -1e30f;
                }
                sa[nj][e] = s;
                if (e < 2) mx0 = fmaxf(mx0, s); else mx1 = fmaxf(mx1, s);
            }
        }
        mx0 = fmaxf(mx0, __shfl_xor_sync(0xffffffffu, mx0, 1));
        mx0 = fmaxf(mx0, __shfl_xor_sync(0xffffffffu, mx0, 2));
        mx1 = fmaxf(mx1, __shfl_xor_sync(0xffffffffu, mx1, 1));
        mx1 = fmaxf(mx1, __shfl_xor_sync(0xffffffffu, mx1, 2));
        float mn0 = fmaxf(m0, mx0), mn1 = fmaxf(m1, mx1);
        float cr0 = __expf(m0 - mn0), cr1 = __expf(m1 - mn1);
        m0 = mn0; m1 = mn1;

        float ls0 = 0.f, ls1 = 0.f;
        unsigned pf[2][4][4];
        #pragma unroll
        for (int nj = 0; nj < 8; nj++) {
            float p0 = __expf(sa[nj][0] - mn0);
            float p1 = __expf(sa[nj][1] - mn0);
            float p2 = __expf(sa[nj][2] - mn1);
            float p3 = __expf(sa[nj][3] - mn1);
            ls0 += p0 + p1; ls1 += p2 + p3;
            bf16 h0 = __float2bfloat16(p0), h1b = __float2bfloat16(p1);
            bf16 h2 = __float2bfloat16(p2), h3b = __float2bfloat16(p3);
            int kt = nj >> 1, off = (nj & 1) * 2;
            pf[0][kt][off]   = pack2(h0, h1b);
            pf[0][kt][off+1] = pack2(h2, h3b);
            pf[1][kt][off]   = packf2(p0 - __bfloat162float(h0), p1 - __bfloat162float(h1b));
            pf[1][kt][off+1] = packf2(p2 - __bfloat162float(h2), p3 - __bfloat162float(h3b));
        }
        ls0 += __shfl_xor_sync(0xffffffffu, ls0, 1);
        ls0 += __shfl_xor_sync(0xffffffffu, ls0, 2);
        ls1 += __shfl_xor_sync(0xffffffffu, ls1, 1);
        ls1 += __shfl_xor_sync(0xffffffffu, ls1, 2);
        l0 = l0 * cr0 + ls0;
        l1 = l1 * cr1 + ls1;
        #pragma unroll
        for (int od = 0; od < 8; od++) {
            oa[od][0] *= cr0; oa[od][1] *= cr0;
            oa[od][2] *= cr1; oa[od][3] *= cr1;
        }

        #pragma unroll
        for (int kt = 0; kt < 4; kt++) {
            #pragma unroll
            for (int odp = 0; odp < 4; odp++) {
                unsigned vh0,vh1,vh2,vh3, vl0,vl1,vl2,vl3;
                unsigned ah = (unsigned)__cvta_generic_to_shared(
                    &Vsh[(kt*16 + vbk)*FP + odp*16 + vbn]);
                unsigned al = (unsigned)__cvta_generic_to_shared(
                    &Vsl[(kt*16 + vbk)*FP + odp*16 + vbn]);
                LDSM_X4T(vh0, vh1, vh2, vh3, ah);
                LDSM_X4T(vl0, vl1, vl2, vl3, al);
                unsigned bvh0[2] = {vh0,vh1}, bvh1[2] = {vh2,vh3};
                unsigned bvl0[2] = {vl0,vl1}, bvl1[2] = {vl2,vl3};
                mma16816(oa[odp*2],   pf[0][kt], bvh0);
                mma16816(oa[odp*2],   pf[0][kt], bvl0);
                mma16816(oa[odp*2],   pf[1][kt], bvh0);
                mma16816(oa[odp*2+1], pf[0][kt], bvh1);
                mma16816(oa[odp*2+1], pf[0][kt], bvl1);
                mma16816(oa[odp*2+1], pf[1][kt], bvh1);
            }
        }
        __syncthreads();
    }

    float i0 = 1.f / l0, i1 = 1.f / l1;
    size_t t0 = ((size_t)(b*SS + qr0))*DIM + h*DH;
    size_t t1 = t0 + (size_t)8*DIM;
    #pragma unroll
    for (int od = 0; od < 8; od++) {
        int col = od*8 + c2;
        float v0 = oa[od][0]*i0, v1 = oa[od][1]*i0;
        float v2 = oa[od][2]*i1, v3 = oa[od][3]*i1;
        bf16 h0 = __float2bfloat16(v0), h1b = __float2bfloat16(v1);
        bf16 h2 = __float2bfloat16(v2), h3b = __float2bfloat16(v3);
        *(unsigned*)&g_o_h[t0 + col] = pack2(h0, h1b);
        *(unsigned*)&g_o_l[t0 + col] = packf2(v0 - __bfloat162float(h0), v1 - __bfloat162float(h1b));
        *(unsigned*)&g_o_h[t1 + col] = pack2(h2, h3b);
        *(unsigned*)&g_o_l[t1 + col] = packf2(v2 - __bfloat162float(h2), v3 - __bfloat162float(h3b));
    }
}

// ---------------- final rmsnorm: warp-per-row, fused split-K residual prologue ----------------
__global__ void __launch_bounds__(256) final_rmsnorm_kernel(const float* __restrict__ fg,
                                float* __restrict__ out,
                                const float* __restrict__ rbias,
                                const float* __restrict__ rgate,
                                const float* __restrict__ rlscale,
                                const int* __restrict__ mod) {
    int row = blockIdx.x * 8 + (threadIdx.x >> 5);
    int lane = threadIdx.x & 31;
    int b = row / SS;
    bool m = mod[row] != 0;
    const float* xr = g_x + (size_t)row * DIM;
    float4 v[4];
    float ss = 0.f;
    #pragma unroll
    for (int j = 0; j < 4; j++) {
        v[j] = *(const float4*)(xr + j*128 + lane*4);
        int i4 = row*128 + j*32 + lane;
        float4 s0 = ((const float4*)g_sk[0])[i4];
        float4 s1 = ((const float4*)g_sk[1])[i4];
        int c = j*128 + lane*4;
        float4 bb = *(const float4*)(rbias + c);
        const float* gsrc = m ? (rgate + b*DIM) : rlscale;
        float4 g4 = *(const float4*)(gsrc + c);
        v[j].x += (s0.x + s1.x + bb.x) * g4.x;
        v[j].y += (s0.y + s1.y + bb.y) * g4.y;
        v[j].z += (s0.z + s1.z + bb.z) * g4.z;
        v[j].w += (s0.w + s1.w + bb.w) * g4.w;
        ss += v[j].x*v[j].x + v[j].y*v[j].y + v[j].z*v[j].z + v[j].w*v[j].w;
    }
    float n = sqrtf(warp_sum(ss));
    float sc = 22.62741699796952f / fmaxf(n, 1e-12f);
    float* outr = out + (size_t)row * DIM;
    #pragma unroll
    for (int j = 0; j < 4; j++) {
        float4 g4 = *(const float4*)(fg + j*128 + lane*4);
        float4 y;
        y.x = v[j].x * sc * (g4.x+1.f);
        y.y = v[j].y * sc * (g4.y+1.f);
        y.z = v[j].z * sc * (g4.z+1.f);
        y.w = v[j].w * sc * (g4.w+1.f);
        *(float4*)(outr + j*128 + lane*4) = y;
    }
}

// ---------------- host ----------------
extern "C" void kernel_launch(void* const* d_in, const int* in_sizes, int n_in,
                              void* d_out, int out_size) {
    const float* x          = (const float*)d_in[0];
    const float* times      = (const float*)d_in[1];
    const int* mod          = (const int*)d_in[3];
    const float* fourier_w  = (const float*)d_in[4];
    const float* time_w     = (const float*)d_in[5];
    const float* time_b     = (const float*)d_in[6];
    const float* aw_ln_g    = (const float*)d_in[7];
    const float* aw_scale   = (const float*)d_in[8];
    const float* aw_film_w  = (const float*)d_in[9];
    const float* aw_film_b  = (const float*)d_in[10];
    const float* aw_zero_w  = (const float*)d_in[11];
    const float* aw_zero_b  = (const float*)d_in[12];
    const float* attn_norm_g= (const float*)d_in[13];
    const float* qkv_w      = (const float*)d_in[14];
    const float* out_w      = (const float*)d_in[15];
    const float* fw_ln_g    = (const float*)d_in[16];
    const float* fw_scale   = (const float*)d_in[17];
    const float* fw_film_w  = (const float*)d_in[18];
    const float* fw_film_b  = (const float*)d_in[19];
    const float* fw_zero_w  = (const float*)d_in[20];
    const float* fw_zero_b  = (const float*)d_in[21];
    const float* ff_norm_g  = (const float*)d_in[22];
    const float* ff_w1      = (const float*)d_in[23];
    const float* ff_b1      = (const float*)d_in[24];
    const float* ff_w2      = (const float*)d_in[25];
    const float* ff_b2      = (const float*)d_in[26];
    const float* final_g    = (const float*)d_in[27];
    float* out = (float*)d_out;

    float *p_femb, *p_cond, *p_film, *p_gate, *p_x, *p_b1p, *p_sk;
    bf16 *p_xin_h, *p_xin_l, *p_o_h, *p_o_l, *p_act_h, *p_act_l;
    bf16 *p_wqkv_h, *p_wqkv_l, *p_wout_h, *p_wout_l, *p_wff1_h, *p_wff1_l, *p_wff2_h, *p_wff2_l;
    cudaGetSymbolAddress((void**)&p_femb, g_femb);
    cudaGetSymbolAddress((void**)&p_cond, g_cond);
    cudaGetSymbolAddress((void**)&p_film, g_film);
    cudaGetSymbolAddress((void**)&p_gate, g_gate);
    cudaGetSymbolAddress((void**)&p_x,    g_x);
    cudaGetSymbolAddress((void**)&p_b1p,  g_b1p);
    cudaGetSymbolAddress((void**)&p_sk,   g_sk);
    cudaGetSymbolAddress((void**)&p_xin_h, g_xin_h);
    cudaGetSymbolAddress((void**)&p_xin_l, g_xin_l);
    cudaGetSymbolAddress((void**)&p_o_h,   g_o_h);
    cudaGetSymbolAddress((void**)&p_o_l,   g_o_l);
    cudaGetSymbolAddress((void**)&p_act_h, g_act_h);
    cudaGetSymbolAddress((void**)&p_act_l, g_act_l);
    cudaGetSymbolAddress((void**)&p_wqkv_h, g_wqkv_h);
    cudaGetSymbolAddress((void**)&p_wqkv_l, g_wqkv_l);
    cudaGetSymbolAddress((void**)&p_wout_h, g_wout_h);
    cudaGetSymbolAddress((void**)&p_wout_l, g_wout_l);
    cudaGetSymbolAddress((void**)&p_wff1_h, g_wff1_h);
    cudaGetSymbolAddress((void**)&p_wff1_l, g_wff1_l);
    cudaGetSymbolAddress((void**)&p_wff2_h, g_wff2_h);
    cudaGetSymbolAddress((void**)&p_wff2_l, g_wff2_l);

    static bool attr_set = false;
    if (!attr_set) {
        cudaFuncSetAttribute(mma_gemm_kernel,
                             cudaFuncAttributeMaxDynamicSharedMemorySize, GEMM_SMEM);
        cudaFuncSetAttribute(flash_mma_kernel,
                             cudaFuncAttributeMaxDynamicSharedMemorySize, FLASH_SMEM);
        attr_set = true;
    }

    copy_x_kernel<<<(NT*DIM + 255)/256, 256>>>(x);

    {
        int n1 = NL*DIM*3*DIM/4;
        split_kernel<<<(n1+255)/256, 256>>>(qkv_w, p_wqkv_h, p_wqkv_l, n1);
        int n2 = NL*DIM*DIM/4;
        split_kernel<<<(n2+255)/256, 256>>>(out_w, p_wout_h, p_wout_l, n2);
        size_t n3 = (size_t)NL*DIM*2*FFIP/4;
        split_ff1_kernel<<<(unsigned)((n3+255)/256), 256>>>(ff_w1);
        size_t n4 = (size_t)NL*FFIP*DIM/4;
        split_ff2_kernel<<<(unsigned)((n4+255)/256), 256>>>(ff_w2);
        pad_b1_kernel<<<(NL*2*FFIP+255)/256, 256>>>(ff_b1);
    }

    femb_kernel<<<(BB*(DIM+1) + 255)/256, 256>>>(times, fourier_w);
    cond_mm_kernel<<<dim3(DC/128, BB*4, 1), 128>>>(p_femb, time_w, DC, DIM+1, 129, 4);
    cond_reduce_kernel<<<(BB*DC+255)/256, 256>>>(time_b, p_cond, DC, 4, 1);

    cond_mm2_kernel<<<dim3((2*DIM)/128, BB*8, 2*NL), 128>>>(
        p_cond, aw_film_w, fw_film_w, 2*DIM, DC, 256, 8);
    cond_reduce2_kernel<<<(2*NL*BB*2*DIM+255)/256, 256>>>(
        aw_film_b, fw_film_b, p_film, 2*DIM, 8, 0);
    cond_mm2_kernel<<<dim3(DIM/128, BB*8, 2*NL), 128>>>(
        p_cond, aw_zero_w, fw_zero_w, DIM, DC, 256, 8);
    cond_reduce2_kernel<<<(2*NL*BB*DIM+255)/256, 256>>>(
        aw_zero_b, fw_zero_b, p_gate, DIM, 8, 2);

    for (int l = 0; l < NL; l++) {
        // ---- attention branch ----
        // fuse previous layer's FF residual (if any)
        if (l == 0) {
            modulate_kernel<<<NT/8, 256>>>(p_x, p_xin_h, p_xin_l,
                p_film + ((size_t)(0*NL + l))*BB*2*DIM,
                aw_ln_g + (size_t)l*DIM, attn_norm_g + (size_t)l*DIM, mod,
                nullptr, nullptr, nullptr, 0);
        } else {
            modulate_kernel<<<NT/8, 256>>>(p_x, p_xin_h, p_xin_l,
                p_film + ((size_t)(0*NL + l))*BB*2*DIM,
                aw_ln_g + (size_t)l*DIM, attn_norm_g + (size_t)l*DIM, mod,
                ff_b2 + (size_t)(l-1)*DIM,
                p_gate + ((size_t)(1*NL + (l-1)))*BB*DIM,
                fw_scale + (size_t)(l-1)*DIM, 1);
        }
        mma_gemm_kernel<<<dim3((3*DIM)/128, NT/128), 256, GEMM_SMEM>>>(
            p_xin_h, p_xin_l,
            p_wqkv_h + (size_t)l*DIM*3*DIM, p_wqkv_l + (size_t)l*DIM*3*DIM,
            nullptr, nullptr, NT, 3*DIM, DIM, 1, nullptr, nullptr, nullptr);
        flash_mma_kernel<<<dim3(SS/64, NH, BB), 128, FLASH_SMEM>>>();
        mma_gemm_kernel<<<dim3(DIM/128, NT/128, 2), 256, GEMM_SMEM>>>(
            p_o_h, p_o_l,
            p_wout_h + (size_t)l*DIM*DIM, p_wout_l + (size_t)l*DIM*DIM,
            nullptr, p_sk, NT, DIM, DIM, 4, nullptr, nullptr, nullptr);

        // ---- feedforward branch (modulate fuses attention residual) ----
        modulate_kernel<<<NT/8, 256>>>(p_x, p_xin_h, p_xin_l,
            p_film + ((size_t)(1*NL + l))*BB*2*DIM,
            fw_ln_g + (size_t)l*DIM, ff_norm_g + (size_t)l*DIM, mod,
            nullptr,
            p_gate + ((size_t)(0*NL + l))*BB*DIM,
            aw_scale + (size_t)l*DIM, 1);
        mma_gemm_kernel<<<dim3((2*FFIP)/128, NT/128), 256, GEMM_SMEM>>>(
            p_xin_h, p_xin_l,
            p_wff1_h + (size_t)l*DIM*2*FFIP, p_wff1_l + (size_t)l*DIM*2*FFIP,
            p_b1p + (size_t)l*2*FFIP, nullptr, NT, 2*FFIP, DIM, 3, nullptr, nullptr, nullptr);
        mma_gemm_kernel<<<dim3(DIM/128, NT/128, 2), 256, GEMM_SMEM>>>(
            p_act_h, p_act_l,
            p_wff2_h + (size_t)l*FFIP*DIM, p_wff2_l + (size_t)l*FFIP*DIM,
            nullptr, p_sk, NT, DIM, FFIP, 4, nullptr, nullptr, nullptr);
    }

    // final rmsnorm fuses the last FF residual
    final_rmsnorm_kernel<<<NT/8, 256>>>(final_g, out,
        ff_b2 + (size_t)(NL-1)*DIM,
        p_gate + ((size_t)(1*NL + (NL-1)))*BB*DIM,
        fw_scale + (size_t)(NL-1)*DIM, mod);
}